// round 1
// baseline (speedup 1.0000x reference)
#include <cuda_runtime.h>
#include <math.h>

// Problem constants
#define Bc   32
#define Nn   256
#define Hh   1024
#define HEADS 8
#define NHID 128
#define NCLS 7
#define BAND 24
#define ROWS (Bc*Nn)          // 8192
#define ALPHA_LRELU 0.2f

// ---------------- device scratch (no allocs allowed) ----------------
__device__ float g_fea_cls[ROWS*Hh];
__device__ float g_fea_emo[ROWS*Hh];
__device__ float g_Wg[Hh*Hh];
__device__ float g_Wh[ROWS*Hh];
__device__ float g_s1[ROWS*HEADS];
__device__ float g_s2[ROWS*HEADS];
__device__ float g_mean1[Bc*Hh];
__device__ float g_h1[ROWS*Hh];
__device__ float g_Wh2[ROWS*Hh];
__device__ float g_s1b[ROWS];
__device__ float g_s2b[ROWS];
__device__ float g_mean2[Bc*Hh];
__device__ float g_h2[ROWS*Hh];
__device__ float g_t1[ROWS*Hh];
__device__ float g_gfin[ROWS*Hh];
__device__ float g_loggat[ROWS*NCLS];
__device__ float g_Bprob[ROWS*NCLS];
__device__ float g_loghmm[ROWS*NCLS];
__device__ float g_blocksums[32];

// ---------------- SGEMM: C[M,N] = A[M,K] @ B[K,N] (+bias, tanh, beta*C) ----
// M%128==0, N%128==0, K%16==0 required (holds for all uses here).
#define BM 128
#define BN 128
#define BK 16
#define TM 8
#define TN 8

__global__ void sgemm_kernel(const float* __restrict__ A,
                             const float* __restrict__ B,
                             float* __restrict__ C,
                             int M, int N, int K,
                             const float* __restrict__ bias,
                             int dotanh, float beta)
{
    __shared__ float As[BK][BM];
    __shared__ float Bs[BK][BN];
    const int bx = blockIdx.x;   // N tile
    const int by = blockIdx.y;   // M tile
    const int tid = threadIdx.x; // 0..255
    const int tx = tid & 15;
    const int ty = tid >> 4;

    float acc[TM][TN];
#pragma unroll
    for (int i = 0; i < TM; i++)
#pragma unroll
        for (int j = 0; j < TN; j++) acc[i][j] = 0.f;

    const float* Aptr = A + (size_t)by * BM * K;
    const float* Bptr = B + (size_t)bx * BN;

    for (int k0 = 0; k0 < K; k0 += BK) {
        // load A tile (128x16) as 512 float4, 2 per thread, store transposed
#pragma unroll
        for (int i = 0; i < 2; i++) {
            int l = tid * 2 + i;            // 0..511
            int row = l >> 2;               // 0..127
            int c4 = (l & 3) << 2;          // 0,4,8,12
            float4 v = *(const float4*)(Aptr + (size_t)row * K + k0 + c4);
            As[c4 + 0][row] = v.x;
            As[c4 + 1][row] = v.y;
            As[c4 + 2][row] = v.z;
            As[c4 + 3][row] = v.w;
        }
        // load B tile (16x128) as 512 float4, 2 per thread
#pragma unroll
        for (int i = 0; i < 2; i++) {
            int l = tid * 2 + i;
            int row = l >> 5;               // 0..15
            int c4 = (l & 31) << 2;         // 0..124
            *(float4*)&Bs[row][c4] = *(const float4*)(Bptr + (size_t)(k0 + row) * N + c4);
        }
        __syncthreads();
#pragma unroll
        for (int kk = 0; kk < BK; kk++) {
            float a[TM], b[TN];
#pragma unroll
            for (int i = 0; i < TM; i++) a[i] = As[kk][ty * TM + i];
#pragma unroll
            for (int j = 0; j < TN; j++) b[j] = Bs[kk][tx * TN + j];
#pragma unroll
            for (int i = 0; i < TM; i++)
#pragma unroll
                for (int j = 0; j < TN; j++) acc[i][j] += a[i] * b[j];
        }
        __syncthreads();
    }

#pragma unroll
    for (int i = 0; i < TM; i++) {
        int row = by * BM + ty * TM + i;
#pragma unroll
        for (int j = 0; j < TN; j++) {
            int col = bx * BN + tx * TN + j;
            float v = acc[i][j];
            if (beta != 0.f) v += beta * C[(size_t)row * N + col];
            if (bias) v += bias[col];
            if (dotanh) v = tanhf(v);
            C[(size_t)row * N + col] = v;
        }
    }
}

// ---------------- misc small kernels ----------------
__global__ void repack_gatW_kernel(const float* __restrict__ gw, float* __restrict__ Wg)
{
    int idx = blockIdx.x * 256 + threadIdx.x;      // f*1024 + c
    int f = idx >> 10;
    int c = idx & 1023;
    int h = c >> 7;
    int d = c & 127;
    Wg[idx] = gw[(h * Hh + f) * NHID + d];
}

// s1[n,h] = Wh[n, h*128..]·a1[h], s2 likewise. 256 threads = 8 warps (1 head/warp).
__global__ void gat_scores_kernel(const float* __restrict__ Wh,
                                  const float* __restrict__ a1,
                                  const float* __restrict__ a2,
                                  float* __restrict__ s1, float* __restrict__ s2)
{
    int n = blockIdx.x;
    int w = threadIdx.x >> 5;
    int l = threadIdx.x & 31;
    const float* row = Wh + (size_t)n * Hh + w * NHID;
    float x1 = 0.f, x2 = 0.f;
#pragma unroll
    for (int t = 0; t < 4; t++) {
        float v = row[l + 32 * t];
        x1 += v * a1[w * NHID + l + 32 * t];
        x2 += v * a2[w * NHID + l + 32 * t];
    }
    for (int o = 16; o > 0; o >>= 1) {
        x1 += __shfl_down_sync(0xffffffffu, x1, o);
        x2 += __shfl_down_sync(0xffffffffu, x2, o);
    }
    if (l == 0) { s1[n * HEADS + w] = x1; s2[n * HEADS + w] = x2; }
}

// column means over the 256 rows of each batch: out[b,c] = mean_n X[b,n,c]
__global__ void mean_rows_kernel(const float* __restrict__ X, float* __restrict__ out)
{
    int b = blockIdx.y;
    int c = blockIdx.x * 256 + threadIdx.x;
    const float* p = X + (size_t)b * Nn * Hh + c;
    float s = 0.f;
    for (int n = 0; n < Nn; n++) s += p[(size_t)n * Hh];
    out[b * Hh + c] = s * (1.0f / Nn);
}

__device__ __forceinline__ float eluf(float x) { return x > 0.f ? x : expf(x) - 1.0f; }

// first GAT attention: block per (b,i), 128 threads, loops over 8 heads
__global__ void gat_att1_kernel(const float* __restrict__ Wh,
                                const float* __restrict__ s1,
                                const float* __restrict__ s2,
                                const float* __restrict__ meanWh,
                                float* __restrict__ h1)
{
    int b = blockIdx.y, i = blockIdx.x, tid = threadIdx.x;
    size_t base = ((size_t)b * Nn + i) * Hh;
    if (i == 0) {
        for (int c = tid; c < Hh; c += 128)
            h1[base + c] = eluf(meanWh[b * Hh + c]);
        return;
    }
    __shared__ float w[32];
    int jlo = i - (BAND - 1); if (jlo < 0) jlo = 0;
    int L = i - jlo;                       // <= 23
    for (int h = 0; h < HEADS; h++) {
        if (tid < L) {
            int j = jlo + tid;
            float e = s1[(b * Nn + i) * HEADS + h] + s2[(b * Nn + j) * HEADS + h];
            w[tid] = e > 0.f ? e : ALPHA_LRELU * e;
        }
        __syncthreads();
        if (tid == 0) {
            float mx = -1e30f;
            for (int t = 0; t < L; t++) mx = fmaxf(mx, w[t]);
            float s = 0.f;
            for (int t = 0; t < L; t++) { float ex = expf(w[t] - mx); w[t] = ex; s += ex; }
            float inv = 1.0f / s;
            for (int t = 0; t < L; t++) w[t] *= inv;
        }
        __syncthreads();
        float acc = 0.f;
        for (int t = 0; t < L; t++)
            acc += w[t] * Wh[((size_t)b * Nn + (jlo + t)) * Hh + h * NHID + tid];
        h1[base + h * NHID + tid] = eluf(acc);
        __syncthreads();
    }
}

// out-layer scores: s1b[n]=Wh2[n]·out_a1, s2b[n]=Wh2[n]·out_a2
__global__ void out_scores_kernel(const float* __restrict__ Wh2,
                                  const float* __restrict__ a1,
                                  const float* __restrict__ a2,
                                  float* __restrict__ s1, float* __restrict__ s2)
{
    int n = blockIdx.x;
    int tid = threadIdx.x;  // 256
    float x1 = 0.f, x2 = 0.f;
    const float* x = Wh2 + (size_t)n * Hh;
    for (int c = tid; c < Hh; c += 256) { float v = x[c]; x1 += v * a1[c]; x2 += v * a2[c]; }
    __shared__ float sh1[8], sh2[8];
    for (int o = 16; o > 0; o >>= 1) {
        x1 += __shfl_down_sync(0xffffffffu, x1, o);
        x2 += __shfl_down_sync(0xffffffffu, x2, o);
    }
    if ((tid & 31) == 0) { sh1[tid >> 5] = x1; sh2[tid >> 5] = x2; }
    __syncthreads();
    if (tid == 0) {
        float t1 = 0.f, t2 = 0.f;
        for (int k = 0; k < 8; k++) { t1 += sh1[k]; t2 += sh2[k]; }
        s1[n] = t1; s2[n] = t2;
    }
}

// second attention (single "head", dim 1024): block per (b,i), 256 threads
__global__ void gat_att2_kernel(const float* __restrict__ Wh2,
                                const float* __restrict__ s1,
                                const float* __restrict__ s2,
                                const float* __restrict__ meanWh2,
                                float* __restrict__ out)
{
    int b = blockIdx.y, i = blockIdx.x, tid = threadIdx.x;
    size_t base = ((size_t)b * Nn + i) * Hh;
    if (i == 0) {
        for (int c = tid; c < Hh; c += 256)
            out[base + c] = eluf(meanWh2[b * Hh + c]);
        return;
    }
    __shared__ float w[32];
    int jlo = i - (BAND - 1); if (jlo < 0) jlo = 0;
    int L = i - jlo;
    if (tid < L) {
        int j = jlo + tid;
        float e = s1[b * Nn + i] + s2[b * Nn + j];
        w[tid] = e > 0.f ? e : ALPHA_LRELU * e;
    }
    __syncthreads();
    if (tid == 0) {
        float mx = -1e30f;
        for (int t = 0; t < L; t++) mx = fmaxf(mx, w[t]);
        float s = 0.f;
        for (int t = 0; t < L; t++) { float ex = expf(w[t] - mx); w[t] = ex; s += ex; }
        float inv = 1.0f / s;
        for (int t = 0; t < L; t++) w[t] *= inv;
    }
    __syncthreads();
    for (int c = tid; c < Hh; c += 256) {
        float acc = 0.f;
        for (int t = 0; t < L; t++)
            acc += w[t] * Wh2[((size_t)b * Nn + (jlo + t)) * Hh + c];
        out[base + c] = eluf(acc);
    }
}

// overwrite row 0 of g with fea_cls row 0 (per batch)
__global__ void row0_kernel(const float* __restrict__ fea, float* __restrict__ g)
{
    int b = blockIdx.x;
    for (int c = threadIdx.x; c < Hh; c += 256)
        g[(size_t)b * Nn * Hh + c] = fea[(size_t)b * Nn * Hh + c];
}

// softmax(classifier(X)) -> probs [ROWS, 7]. 224 threads = 7 warps, warp k = class k.
__global__ void cls_softmax_kernel(const float* __restrict__ X,
                                   const float* __restrict__ W,
                                   const float* __restrict__ bcls,
                                   float* __restrict__ out)
{
    int n = blockIdx.x;
    int wid = threadIdx.x >> 5;
    int l = threadIdx.x & 31;
    __shared__ float sh[NCLS];
    const float* x = X + (size_t)n * Hh;
    float acc = 0.f;
    for (int t = l; t < Hh; t += 32) acc += x[t] * W[t * NCLS + wid];
    for (int o = 16; o > 0; o >>= 1) acc += __shfl_down_sync(0xffffffffu, acc, o);
    if (l == 0) sh[wid] = acc + bcls[wid];
    __syncthreads();
    if (threadIdx.x == 0) {
        float mx = sh[0];
        for (int k = 1; k < NCLS; k++) mx = fmaxf(mx, sh[k]);
        float e[NCLS], s = 0.f;
        for (int k = 0; k < NCLS; k++) { e[k] = expf(sh[k] - mx); s += e[k]; }
        float inv = 1.0f / s;
        for (int k = 0; k < NCLS; k++) out[n * NCLS + k] = e[k] * inv;
    }
}

// HMM forward filter per (b,i) over the band window [max(0,i-23), i]
__global__ void hmm_kernel(const float* __restrict__ Bprob,
                           const float* __restrict__ hmmA,
                           float* __restrict__ out)
{
    __shared__ float sAT[NCLS * NCLS];     // AT[r][c] = A[c][r]
    int tid = threadIdx.x;
    if (tid < NCLS * NCLS) sAT[tid] = hmmA[(tid % NCLS) * NCLS + (tid / NCLS)];
    __syncthreads();
    int gidx = blockIdx.x * 128 + tid;     // 0..8191
    int b = gidx >> 8;
    int i = gidx & 255;
    const float* Bp = Bprob + (size_t)b * Nn * NCLS;
    int t0 = i - (BAND - 1); if (t0 < 0) t0 = 0;
    float p[NCLS];
    float s = 0.f;
#pragma unroll
    for (int r = 0; r < NCLS; r++) { p[r] = Bp[t0 * NCLS + r]; s += p[r]; } // uniform P0 cancels
    float inv = 1.0f / s;
#pragma unroll
    for (int r = 0; r < NCLS; r++) p[r] *= inv;
    for (int t = t0 + 1; t <= i; t++) {
        float q[NCLS];
        s = 0.f;
#pragma unroll
        for (int r = 0; r < NCLS; r++) {
            float a = 0.f;
#pragma unroll
            for (int c = 0; c < NCLS; c++) a += sAT[r * NCLS + c] * p[c];
            a *= Bp[t * NCLS + r];
            q[r] = a; s += a;
        }
        inv = 1.0f / s;
#pragma unroll
        for (int r = 0; r < NCLS; r++) p[r] = q[r] * inv;
    }
#pragma unroll
    for (int r = 0; r < NCLS; r++) out[gidx * NCLS + r] = p[r];
}

// final logits + per-block loss partial sums (deterministic)
__global__ void final_kernel(const float* __restrict__ log_gat,
                             const float* __restrict__ log_hmm,
                             const int* __restrict__ labels,
                             float* __restrict__ outLogits)
{
    int r = blockIdx.x * 256 + threadIdx.x;
    float lg[NCLS];
#pragma unroll
    for (int k = 0; k < NCLS; k++) {
        lg[k] = logf(0.5f * (log_gat[r * NCLS + k] + log_hmm[r * NCLS + k]));
        outLogits[r * NCLS + k] = lg[k];
    }
    int lab = labels[r];
    float picked = (lab >= 0) ? lg[lab] : 0.f;
    for (int o = 16; o > 0; o >>= 1) picked += __shfl_down_sync(0xffffffffu, picked, o);
    __shared__ float sh[8];
    if ((threadIdx.x & 31) == 0) sh[threadIdx.x >> 5] = picked;
    __syncthreads();
    if (threadIdx.x == 0) {
        float s = 0.f;
        for (int k = 0; k < 8; k++) s += sh[k];
        g_blocksums[blockIdx.x] = s;
    }
}

__global__ void finalize_kernel(float* d_out, int has_loss)
{
    if (has_loss) {
        float s = 0.f;
        for (int k = 0; k < 32; k++) s += g_blocksums[k];
        d_out[0] = -s / (float)ROWS;
    }
}

// ---------------- host launch ----------------
static void sgemm(const float* A, const float* B, float* C, int M, int N, int K,
                  const float* bias, int dotanh, float beta)
{
    dim3 grid(N / BN, M / BM);
    sgemm_kernel<<<grid, 256>>>(A, B, C, M, N, K, bias, dotanh, beta);
}

template <typename T>
static T* sym(const void* symbol)
{
    void* p = nullptr;
    cudaGetSymbolAddress(&p, symbol);
    return (T*)p;
}

extern "C" void kernel_launch(void* const* d_in, const int* in_sizes, int n_in,
                              void* d_out, int out_size)
{
    (void)in_sizes; (void)n_in;
    const float* hidden_cls = (const float*)d_in[0];
    const float* hidden_emo = (const float*)d_in[1];
    // d_in[2] = clique (band structure known analytically; unused)
    const int*   labels     = (const int*)d_in[3];
    const float* pooler_W   = (const float*)d_in[4];
    const float* pooler_b   = (const float*)d_in[5];
    const float* gat_W      = (const float*)d_in[6];
    const float* gat_a1     = (const float*)d_in[7];
    const float* gat_a2     = (const float*)d_in[8];
    const float* out_W      = (const float*)d_in[9];
    const float* out_a1     = (const float*)d_in[10];
    const float* out_a2     = (const float*)d_in[11];
    const float* lin1_W     = (const float*)d_in[12];
    const float* lin1_b     = (const float*)d_in[13];
    const float* lin0_W     = (const float*)d_in[14];
    const float* lin0_b     = (const float*)d_in[15];
    const float* cls_W      = (const float*)d_in[16];
    const float* cls_b      = (const float*)d_in[17];
    const float* hmm_A      = (const float*)d_in[18];

    float* fea_cls = sym<float>(g_fea_cls);
    float* fea_emo = sym<float>(g_fea_emo);
    float* Wg      = sym<float>(g_Wg);
    float* Wh      = sym<float>(g_Wh);
    float* s1      = sym<float>(g_s1);
    float* s2      = sym<float>(g_s2);
    float* mean1   = sym<float>(g_mean1);
    float* h1      = sym<float>(g_h1);
    float* Wh2     = sym<float>(g_Wh2);
    float* s1b     = sym<float>(g_s1b);
    float* s2b     = sym<float>(g_s2b);
    float* mean2   = sym<float>(g_mean2);
    float* h2      = sym<float>(g_h2);
    float* t1      = sym<float>(g_t1);
    float* gfin    = sym<float>(g_gfin);
    float* loggat  = sym<float>(g_loggat);
    float* Bprob   = sym<float>(g_Bprob);
    float* loghmm  = sym<float>(g_loghmm);

    int has_loss = (out_size == ROWS * NCLS + 1) ? 1 : 0;
    float* outLogits = has_loss ? ((float*)d_out + 1) : (float*)d_out;

    // 1) poolers
    sgemm(hidden_cls, pooler_W, fea_cls, ROWS, Hh, Hh, pooler_b, 1, 0.f);
    sgemm(hidden_emo, pooler_W, fea_emo, ROWS, Hh, Hh, pooler_b, 1, 0.f);

    // 2) GAT layer 1
    repack_gatW_kernel<<<(Hh * Hh) / 256, 256>>>(gat_W, Wg);
    sgemm(fea_cls, Wg, Wh, ROWS, Hh, Hh, nullptr, 0, 0.f);
    gat_scores_kernel<<<ROWS, 256>>>(Wh, gat_a1, gat_a2, s1, s2);
    mean_rows_kernel<<<dim3(Hh / 256, Bc), 256>>>(Wh, mean1);
    gat_att1_kernel<<<dim3(Nn, Bc), 128>>>(Wh, s1, s2, mean1, h1);

    // 3) GAT out layer
    sgemm(h1, out_W, Wh2, ROWS, Hh, Hh, nullptr, 0, 0.f);
    out_scores_kernel<<<ROWS, 256>>>(Wh2, out_a1, out_a2, s1b, s2b);
    mean_rows_kernel<<<dim3(Hh / 256, Bc), 256>>>(Wh2, mean2);
    gat_att2_kernel<<<dim3(Nn, Bc), 256>>>(Wh2, s1b, s2b, mean2, h2);

    // 4) g (row0 <- fea_cls row0), lin1, lin0 (K=2048 split into two passes)
    row0_kernel<<<Bc, 256>>>(fea_cls, h2);
    sgemm(h2, lin1_W, t1, ROWS, Hh, Hh, lin1_b, 0, 0.f);
    sgemm(fea_cls, lin0_W, gfin, ROWS, Hh, Hh, nullptr, 0, 0.f);
    sgemm(t1, lin0_W + (size_t)Hh * Hh, gfin, ROWS, Hh, Hh, lin0_b, 0, 1.f);

    // 5) classifier softmaxes
    cls_softmax_kernel<<<ROWS, 224>>>(gfin, cls_W, cls_b, loggat);
    cls_softmax_kernel<<<ROWS, 224>>>(fea_emo, cls_W, cls_b, Bprob);

    // 6) HMM band filter
    hmm_kernel<<<ROWS / 128, 128>>>(Bprob, hmm_A, loghmm);

    // 7) final logits + loss
    final_kernel<<<ROWS / 256, 256>>>(loggat, loghmm, labels, outLogits);
    finalize_kernel<<<1, 1>>>((float*)d_out, has_loss);
}

// round 4
// speedup vs baseline: 3.3385x; 3.3385x over previous
#include <cuda_runtime.h>
#include <math.h>
#include <stdint.h>

// Problem constants
#define Bc   32
#define Nn   256
#define Hh   1024
#define HEADS 8
#define NHID 128
#define NCLS 7
#define BAND 24
#define ROWS (Bc*Nn)          // 8192
#define ALPHA_LRELU 0.2f

// ---------------- device scratch (no allocs allowed) ----------------
__device__ float g_fea_cls[ROWS*Hh];
__device__ float g_fea_emo[ROWS*Hh];
__device__ float g_Wh[ROWS*Hh];
__device__ float g_h1[ROWS*Hh];
__device__ float g_Wh2[ROWS*Hh];
__device__ float g_h2[ROWS*Hh];
__device__ float g_t1[ROWS*Hh];
__device__ float g_gfin[ROWS*Hh];
__device__ float g_s1[ROWS*HEADS];
__device__ float g_s2[ROWS*HEADS];
__device__ float g_s1b[ROWS];
__device__ float g_s2b[ROWS];
__device__ float g_mean1[Bc*Hh];
__device__ float g_loggat[ROWS*NCLS];
__device__ float g_Bprob[ROWS*NCLS];
__device__ float g_loghmm[ROWS*NCLS];
__device__ float g_blocksums[32];
// transposed weights ([N][K] K-major, B operand)
__device__ float g_poolWt[Hh*Hh];
__device__ float g_Wgt[Hh*Hh];
__device__ float g_outWt[Hh*Hh];
__device__ float g_lin1Wt[Hh*Hh];
__device__ float g_lin0Wt[Hh*2*Hh];

// =================== mma.sync tf32 GEMM ===================
// C[M,N-tile] = A[M,K] @ Bt^T, Bt is [N][K] row-major. A optionally split
// into two K-sources (concat GEMM). Fused bias / tanh epilogue.
#define BM 128
#define BN 128
#define BKg 32
#define LDS_PAD 4
#define TILE_LD (BKg + LDS_PAD)              // 36 floats per row
#define STAGE_FLOATS (2 * BM * TILE_LD)      // A + B per stage = 9216
#define GEMM_SMEM (2 * STAGE_FLOATS * 4)     // 73728 bytes

__device__ __forceinline__ uint32_t smem_u32(const void* p) {
    uint32_t a;
    asm("{ .reg .u64 t; cvta.to.shared.u64 t, %1; cvt.u32.u64 %0, t; }" : "=r"(a) : "l"(p));
    return a;
}
__device__ __forceinline__ void cp16(uint32_t s, const void* g) {
    asm volatile("cp.async.cg.shared.global [%0], [%1], 16;" :: "r"(s), "l"(g));
}
#define CP_COMMIT() asm volatile("cp.async.commit_group;" ::: "memory")
#define CP_WAIT0()  asm volatile("cp.async.wait_group 0;" ::: "memory")

__device__ __forceinline__ uint32_t f2tf32(float v) {
    uint32_t t;
    asm("cvt.rna.tf32.f32 %0, %1;" : "=r"(t) : "f"(v));
    return t;
}
__device__ __forceinline__ void mma_tf32(float& d0, float& d1, float& d2, float& d3,
                                         uint32_t a0, uint32_t a1, uint32_t a2, uint32_t a3,
                                         uint32_t b0, uint32_t b1) {
    asm volatile("mma.sync.aligned.m16n8k8.row.col.f32.tf32.tf32.f32 "
                 "{%0,%1,%2,%3}, {%4,%5,%6,%7}, {%8,%9}, {%0,%1,%2,%3};"
                 : "+f"(d0), "+f"(d1), "+f"(d2), "+f"(d3)
                 : "r"(a0), "r"(a1), "r"(a2), "r"(a3), "r"(b0), "r"(b1));
}

// stage layout: [stage][ A: BM x TILE_LD | B: BN x TILE_LD ]
__device__ __forceinline__ void gemm_load_stage(uint32_t sb, int stage, int tid,
                                                const float* Ag, const float* Bg, int ldb) {
    uint32_t abase = sb + stage * (STAGE_FLOATS * 4);
    uint32_t bbase = abase + BM * TILE_LD * 4;
#pragma unroll
    for (int i = 0; i < 4; i++) {
        int idx = tid + 256 * i;        // 0..1023
        int r = idx >> 3;               // 0..127
        int q = idx & 7;                // float4 index in 32-float row
        cp16(abase + (r * TILE_LD + q * 4) * 4, Ag + (size_t)r * Hh + q * 4);
        cp16(bbase + (r * TILE_LD + q * 4) * 4, Bg + (size_t)r * ldb + q * 4);
    }
}

__global__ void __launch_bounds__(256, 2)
mma_gemm(const float* __restrict__ A1, const float* __restrict__ A2, int ksplit,
         int T, const float* __restrict__ Bt, int ldb,
         float* __restrict__ C, const float* __restrict__ bias, int dotanh)
{
    extern __shared__ char smem[];
    uint32_t sb = smem_u32(smem);
    float* sbase = (float*)smem;
    const int tid = threadIdx.x;
    const int wid = tid >> 5, lane = tid & 31;
    const int wm = wid >> 2, wn = wid & 3;   // 2x4 warp grid, warp tile 64x32
    const int n0 = blockIdx.x * BN;
    const size_t m0 = (size_t)blockIdx.y * BM;

    float acc[4][4][4];
#pragma unroll
    for (int mi = 0; mi < 4; mi++)
#pragma unroll
        for (int ni = 0; ni < 4; ni++)
#pragma unroll
            for (int k = 0; k < 4; k++) acc[mi][ni][k] = 0.f;

    const float* Brow = Bt + (size_t)n0 * ldb;
    // prologue
    {
        const float* Ag = (0 < ksplit ? A1 : A2) + m0 * Hh;
        gemm_load_stage(sb, 0, tid, Ag, Brow, ldb);
        CP_COMMIT();
    }

    const int lq = lane >> 2;   // 0..7
    const int lr = lane & 3;    // 0..3

    for (int t = 0; t < T; t++) {
        CP_WAIT0();
        __syncthreads();
        // prefetch next stage
        if (t + 1 < T) {
            int nc = t + 1;
            const float* Ag = (nc < ksplit ? A1 + nc * BKg : A2 + (nc - ksplit) * BKg) + m0 * Hh;
            gemm_load_stage(sb, (t + 1) & 1, tid, Ag, Brow + nc * BKg, ldb);
            CP_COMMIT();
        }
        const float* sA = sbase + (t & 1) * STAGE_FLOATS;
        const float* sB = sA + BM * TILE_LD;
#pragma unroll
        for (int kk = 0; kk < BKg; kk += 8) {
            uint32_t af[4][4];
#pragma unroll
            for (int mi = 0; mi < 4; mi++) {
                const float* ap = sA + (wm * 64 + mi * 16 + lq) * TILE_LD + kk + lr;
                af[mi][0] = f2tf32(ap[0]);
                af[mi][1] = f2tf32(ap[8 * TILE_LD]);
                af[mi][2] = f2tf32(ap[4]);
                af[mi][3] = f2tf32(ap[8 * TILE_LD + 4]);
            }
            uint32_t bf[4][2];
#pragma unroll
            for (int ni = 0; ni < 4; ni++) {
                const float* bp = sB + (wn * 32 + ni * 8 + lq) * TILE_LD + kk + lr;
                bf[ni][0] = f2tf32(bp[0]);
                bf[ni][1] = f2tf32(bp[4]);
            }
#pragma unroll
            for (int mi = 0; mi < 4; mi++)
#pragma unroll
                for (int ni = 0; ni < 4; ni++)
                    mma_tf32(acc[mi][ni][0], acc[mi][ni][1], acc[mi][ni][2], acc[mi][ni][3],
                             af[mi][0], af[mi][1], af[mi][2], af[mi][3],
                             bf[ni][0], bf[ni][1]);
        }
        __syncthreads();
    }

    // epilogue
#pragma unroll
    for (int mi = 0; mi < 4; mi++) {
        int row = (int)m0 + wm * 64 + mi * 16 + lq;
#pragma unroll
        for (int ni = 0; ni < 4; ni++) {
            int col = n0 + wn * 32 + ni * 8 + lr * 2;
            float b0 = 0.f, b1 = 0.f;
            if (bias) { b0 = bias[col]; b1 = bias[col + 1]; }
            float2 v0, v1;
            v0.x = acc[mi][ni][0] + b0; v0.y = acc[mi][ni][1] + b1;
            v1.x = acc[mi][ni][2] + b0; v1.y = acc[mi][ni][3] + b1;
            if (dotanh) {
                v0.x = tanhf(v0.x); v0.y = tanhf(v0.y);
                v1.x = tanhf(v1.x); v1.y = tanhf(v1.y);
            }
            *(float2*)(C + (size_t)row * Hh + col) = v0;
            *(float2*)(C + (size_t)(row + 8) * Hh + col) = v1;
        }
    }
}

// =================== weight prep ===================
__global__ void transpose_kernel(const float* __restrict__ in, float* __restrict__ out,
                                 int K, int N)
{
    __shared__ float tile[32][33];
    int k0 = blockIdx.y * 32, n0 = blockIdx.x * 32;
    int tx = threadIdx.x, ty = threadIdx.y;
    for (int r = ty; r < 32; r += 8) tile[r][tx] = in[(size_t)(k0 + r) * N + n0 + tx];
    __syncthreads();
    for (int r = ty; r < 32; r += 8) out[(size_t)(n0 + r) * K + k0 + tx] = tile[tx][r];
}
// Wgt[n=h*128+d][f] = gat_W[h][f][d]
__global__ void repack_gatWt_kernel(const float* __restrict__ gw, float* __restrict__ Wgt)
{
    int idx = blockIdx.x * 256 + threadIdx.x;   // n*1024 + f
    int n = idx >> 10, f = idx & 1023;
    int h = n >> 7, d = n & 127;
    Wgt[idx] = gw[((size_t)(h << 10 | f)) * NHID + d];
}

// =================== small kernels ===================
__global__ void gat_scores_kernel(const float* __restrict__ Wh,
                                  const float* __restrict__ a1,
                                  const float* __restrict__ a2,
                                  float* __restrict__ s1, float* __restrict__ s2)
{
    int n = blockIdx.x;
    int w = threadIdx.x >> 5, l = threadIdx.x & 31;
    const float* row = Wh + (size_t)n * Hh + w * NHID;
    float x1 = 0.f, x2 = 0.f;
#pragma unroll
    for (int t = 0; t < 4; t++) {
        float v = row[l + 32 * t];
        x1 += v * a1[w * NHID + l + 32 * t];
        x2 += v * a2[w * NHID + l + 32 * t];
    }
    for (int o = 16; o > 0; o >>= 1) {
        x1 += __shfl_down_sync(0xffffffffu, x1, o);
        x2 += __shfl_down_sync(0xffffffffu, x2, o);
    }
    if (l == 0) { s1[n * HEADS + w] = x1; s2[n * HEADS + w] = x2; }
}

__global__ void mean_rows_kernel(const float* __restrict__ X, float* __restrict__ out)
{
    int b = blockIdx.y;
    int c = blockIdx.x * 256 + threadIdx.x;
    const float* p = X + (size_t)b * Nn * Hh + c;
    float s = 0.f;
    for (int n = 0; n < Nn; n++) s += p[(size_t)n * Hh];
    out[b * Hh + c] = s * (1.0f / Nn);
}

__device__ __forceinline__ float eluf(float x) { return x > 0.f ? x : expf(x) - 1.0f; }

// tiled band attention, layer 1 (per-head). grid(8 i-tiles, 8 heads, 32 batches), 128 thr
__global__ void att1_tile_kernel(const float* __restrict__ Wh,
                                 const float* __restrict__ s1,
                                 const float* __restrict__ s2,
                                 float* __restrict__ h1)
{
    __shared__ float sW[54][128];
    __shared__ float sw[32][24];
    int b = blockIdx.z, h = blockIdx.y, it = blockIdx.x;
    int i0 = it * 32;
    int jlo0 = i0 - 23; if (jlo0 < 0) jlo0 = 0;
    int nrows = (i0 + 30) - jlo0 + 1;
    int tid = threadIdx.x;
    const float* base = Wh + (size_t)b * Nn * Hh + h * NHID;
    for (int rr = 0; rr < nrows; rr++)
        sW[rr][tid] = base[(size_t)(jlo0 + rr) * Hh + tid];
    if (tid < 32) {
        int i = i0 + tid;
        if (i > 0) {
            int jl = i - 23; if (jl < 0) jl = 0;
            int L = i - jl;
            float si = s1[((size_t)b * Nn + i) * HEADS + h];
            float mx = -1e30f;
            for (int t = 0; t < L; t++) {
                float v = si + s2[((size_t)b * Nn + jl + t) * HEADS + h];
                v = v > 0.f ? v : ALPHA_LRELU * v;
                sw[tid][t] = v; mx = fmaxf(mx, v);
            }
            float ssum = 0.f;
            for (int t = 0; t < L; t++) { float ex = expf(sw[tid][t] - mx); sw[tid][t] = ex; ssum += ex; }
            float inv = 1.0f / ssum;
            for (int t = 0; t < L; t++) sw[tid][t] *= inv;
        }
    }
    __syncthreads();
    for (int il = 0; il < 32; il++) {
        int i = i0 + il;
        if (i == 0) continue;
        int jl = i - 23; if (jl < 0) jl = 0;
        int L = i - jl, roff = jl - jlo0;
        float acc = 0.f;
        for (int t = 0; t < L; t++) acc += sw[il][t] * sW[roff + t][tid];
        h1[((size_t)b * Nn + i) * Hh + h * NHID + tid] = eluf(acc);
    }
}

// row 0 of h1 = elu(mean over rows of Wh)
__global__ void att1_row0_kernel(const float* __restrict__ mean1, float* __restrict__ h1)
{
    int b = blockIdx.x;
    for (int c = threadIdx.x; c < Hh; c += 256)
        h1[(size_t)b * Nn * Hh + c] = eluf(mean1[b * Hh + c]);
}

__global__ void out_scores_kernel(const float* __restrict__ Wh2,
                                  const float* __restrict__ a1,
                                  const float* __restrict__ a2,
                                  float* __restrict__ s1, float* __restrict__ s2)
{
    int n = blockIdx.x;
    int tid = threadIdx.x;
    float x1 = 0.f, x2 = 0.f;
    const float* x = Wh2 + (size_t)n * Hh;
    for (int c = tid; c < Hh; c += 256) { float v = x[c]; x1 += v * a1[c]; x2 += v * a2[c]; }
    __shared__ float sh1[8], sh2[8];
    for (int o = 16; o > 0; o >>= 1) {
        x1 += __shfl_down_sync(0xffffffffu, x1, o);
        x2 += __shfl_down_sync(0xffffffffu, x2, o);
    }
    if ((tid & 31) == 0) { sh1[tid >> 5] = x1; sh2[tid >> 5] = x2; }
    __syncthreads();
    if (tid == 0) {
        float t1 = 0.f, t2 = 0.f;
        for (int k = 0; k < 8; k++) { t1 += sh1[k]; t2 += sh2[k]; }
        s1[n] = t1; s2[n] = t2;
    }
}

// tiled band attention, out layer. grid(8 i-tiles, 8 col-tiles, 32 batches), 128 thr
__global__ void att2_tile_kernel(const float* __restrict__ Wh2,
                                 const float* __restrict__ s1,
                                 const float* __restrict__ s2,
                                 float* __restrict__ out)
{
    __shared__ float sW[54][128];
    __shared__ float sw[32][24];
    int b = blockIdx.z, ct = blockIdx.y, it = blockIdx.x;
    int i0 = it * 32, c0 = ct * 128;
    int jlo0 = i0 - 23; if (jlo0 < 0) jlo0 = 0;
    int nrows = (i0 + 30) - jlo0 + 1;
    int tid = threadIdx.x;
    const float* base = Wh2 + (size_t)b * Nn * Hh + c0;
    for (int rr = 0; rr < nrows; rr++)
        sW[rr][tid] = base[(size_t)(jlo0 + rr) * Hh + tid];
    if (tid < 32) {
        int i = i0 + tid;
        if (i > 0) {
            int jl = i - 23; if (jl < 0) jl = 0;
            int L = i - jl;
            float si = s1[(size_t)b * Nn + i];
            float mx = -1e30f;
            for (int t = 0; t < L; t++) {
                float v = si + s2[(size_t)b * Nn + jl + t];
                v = v > 0.f ? v : ALPHA_LRELU * v;
                sw[tid][t] = v; mx = fmaxf(mx, v);
            }
            float ssum = 0.f;
            for (int t = 0; t < L; t++) { float ex = expf(sw[tid][t] - mx); sw[tid][t] = ex; ssum += ex; }
            float inv = 1.0f / ssum;
            for (int t = 0; t < L; t++) sw[tid][t] *= inv;
        }
    }
    __syncthreads();
    for (int il = 0; il < 32; il++) {
        int i = i0 + il;
        if (i == 0) continue;
        int jl = i - 23; if (jl < 0) jl = 0;
        int L = i - jl, roff = jl - jlo0;
        float acc = 0.f;
        for (int t = 0; t < L; t++) acc += sw[il][t] * sW[roff + t][tid];
        out[((size_t)b * Nn + i) * Hh + c0 + tid] = eluf(acc);
    }
}

__global__ void row0_kernel(const float* __restrict__ fea, float* __restrict__ g)
{
    int b = blockIdx.x;
    for (int c = threadIdx.x; c < Hh; c += 256)
        g[(size_t)b * Nn * Hh + c] = fea[(size_t)b * Nn * Hh + c];
}

__global__ void cls_softmax_kernel(const float* __restrict__ X,
                                   const float* __restrict__ W,
                                   const float* __restrict__ bcls,
                                   float* __restrict__ out)
{
    int n = blockIdx.x;
    int wid = threadIdx.x >> 5, l = threadIdx.x & 31;
    __shared__ float sh[NCLS];
    const float* x = X + (size_t)n * Hh;
    float acc = 0.f;
    for (int t = l; t < Hh; t += 32) acc += x[t] * W[t * NCLS + wid];
    for (int o = 16; o > 0; o >>= 1) acc += __shfl_down_sync(0xffffffffu, acc, o);
    if (l == 0) sh[wid] = acc + bcls[wid];
    __syncthreads();
    if (threadIdx.x == 0) {
        float mx = sh[0];
        for (int k = 1; k < NCLS; k++) mx = fmaxf(mx, sh[k]);
        float e[NCLS], s = 0.f;
        for (int k = 0; k < NCLS; k++) { e[k] = expf(sh[k] - mx); s += e[k]; }
        float inv = 1.0f / s;
        for (int k = 0; k < NCLS; k++) out[n * NCLS + k] = e[k] * inv;
    }
}

__global__ void hmm_kernel(const float* __restrict__ Bprob,
                           const float* __restrict__ hmmA,
                           float* __restrict__ out)
{
    __shared__ float sAT[NCLS * NCLS];
    int tid = threadIdx.x;
    if (tid < NCLS * NCLS) sAT[tid] = hmmA[(tid % NCLS) * NCLS + (tid / NCLS)];
    __syncthreads();
    int gidx = blockIdx.x * 128 + tid;
    int b = gidx >> 8, i = gidx & 255;
    const float* Bp = Bprob + (size_t)b * Nn * NCLS;
    int t0 = i - (BAND - 1); if (t0 < 0) t0 = 0;
    float p[NCLS]; float s = 0.f;
#pragma unroll
    for (int r = 0; r < NCLS; r++) { p[r] = Bp[t0 * NCLS + r]; s += p[r]; }
    float inv = 1.0f / s;
#pragma unroll
    for (int r = 0; r < NCLS; r++) p[r] *= inv;
    for (int t = t0 + 1; t <= i; t++) {
        float q[NCLS]; s = 0.f;
#pragma unroll
        for (int r = 0; r < NCLS; r++) {
            float a = 0.f;
#pragma unroll
            for (int c = 0; c < NCLS; c++) a += sAT[r * NCLS + c] * p[c];
            a *= Bp[t * NCLS + r];
            q[r] = a; s += a;
        }
        inv = 1.0f / s;
#pragma unroll
        for (int r = 0; r < NCLS; r++) p[r] = q[r] * inv;
    }
#pragma unroll
    for (int r = 0; r < NCLS; r++) out[gidx * NCLS + r] = p[r];
}

__global__ void final_kernel(const float* __restrict__ log_gat,
                             const float* __restrict__ log_hmm,
                             const int* __restrict__ labels,
                             float* __restrict__ outLogits)
{
    int r = blockIdx.x * 256 + threadIdx.x;
    float lg[NCLS];
#pragma unroll
    for (int k = 0; k < NCLS; k++) {
        lg[k] = logf(0.5f * (log_gat[r * NCLS + k] + log_hmm[r * NCLS + k]));
        outLogits[r * NCLS + k] = lg[k];
    }
    int lab = labels[r];
    float picked = (lab >= 0) ? lg[lab] : 0.f;
    for (int o = 16; o > 0; o >>= 1) picked += __shfl_down_sync(0xffffffffu, picked, o);
    __shared__ float sh[8];
    if ((threadIdx.x & 31) == 0) sh[threadIdx.x >> 5] = picked;
    __syncthreads();
    if (threadIdx.x == 0) {
        float s = 0.f;
        for (int k = 0; k < 8; k++) s += sh[k];
        g_blocksums[blockIdx.x] = s;
    }
}

__global__ void finalize_kernel(float* d_out, int has_loss)
{
    if (has_loss) {
        float s = 0.f;
        for (int k = 0; k < 32; k++) s += g_blocksums[k];
        d_out[0] = -s / (float)ROWS;
    }
}

// ---------------- host launch ----------------
template <typename T>
static T* sym(const void* symbol)
{
    void* p = nullptr;
    cudaGetSymbolAddress(&p, symbol);
    return (T*)p;
}

static void gemm_tc(const float* A1, const float* A2, int ksplit, int T,
                    const float* Bt, int ldb, float* C, const float* bias, int dotanh)
{
    dim3 grid(Hh / BN, ROWS / BM);
    mma_gemm<<<grid, 256, GEMM_SMEM>>>(A1, A2, ksplit, T, Bt, ldb, C, bias, dotanh);
}

extern "C" void kernel_launch(void* const* d_in, const int* in_sizes, int n_in,
                              void* d_out, int out_size)
{
    (void)in_sizes; (void)n_in;
    const float* hidden_cls = (const float*)d_in[0];
    const float* hidden_emo = (const float*)d_in[1];
    const int*   labels     = (const int*)d_in[3];
    const float* pooler_W   = (const float*)d_in[4];
    const float* pooler_b   = (const float*)d_in[5];
    const float* gat_W      = (const float*)d_in[6];
    const float* gat_a1     = (const float*)d_in[7];
    const float* gat_a2     = (const float*)d_in[8];
    const float* out_W      = (const float*)d_in[9];
    const float* out_a1     = (const float*)d_in[10];
    const float* out_a2     = (const float*)d_in[11];
    const float* lin1_W     = (const float*)d_in[12];
    const float* lin1_b     = (const float*)d_in[13];
    const float* lin0_W     = (const float*)d_in[14];
    const float* lin0_b     = (const float*)d_in[15];
    const float* cls_W      = (const float*)d_in[16];
    const float* cls_b      = (const float*)d_in[17];
    const float* hmm_A      = (const float*)d_in[18];

    float* fea_cls = sym<float>(g_fea_cls);
    float* fea_emo = sym<float>(g_fea_emo);
    float* Wh      = sym<float>(g_Wh);
    float* h1      = sym<float>(g_h1);
    float* Wh2     = sym<float>(g_Wh2);
    float* h2      = sym<float>(g_h2);
    float* t1      = sym<float>(g_t1);
    float* gfin    = sym<float>(g_gfin);
    float* s1      = sym<float>(g_s1);
    float* s2      = sym<float>(g_s2);
    float* s1b     = sym<float>(g_s1b);
    float* s2b     = sym<float>(g_s2b);
    float* mean1   = sym<float>(g_mean1);
    float* loggat  = sym<float>(g_loggat);
    float* Bprob   = sym<float>(g_Bprob);
    float* loghmm  = sym<float>(g_loghmm);
    float* poolWt  = sym<float>(g_poolWt);
    float* Wgt     = sym<float>(g_Wgt);
    float* outWt   = sym<float>(g_outWt);
    float* lin1Wt  = sym<float>(g_lin1Wt);
    float* lin0Wt  = sym<float>(g_lin0Wt);

    cudaFuncSetAttribute(mma_gemm, cudaFuncAttributeMaxDynamicSharedMemorySize, GEMM_SMEM);

    int has_loss = (out_size == ROWS * NCLS + 1) ? 1 : 0;
    float* outLogits = has_loss ? ((float*)d_out + 1) : (float*)d_out;

    // 0) weight prep
    {
        dim3 blk(32, 8);
        transpose_kernel<<<dim3(Hh / 32, Hh / 32), blk>>>(pooler_W, poolWt, Hh, Hh);
        transpose_kernel<<<dim3(Hh / 32, Hh / 32), blk>>>(out_W, outWt, Hh, Hh);
        transpose_kernel<<<dim3(Hh / 32, Hh / 32), blk>>>(lin1_W, lin1Wt, Hh, Hh);
        transpose_kernel<<<dim3(Hh / 32, 2 * Hh / 32), blk>>>(lin0_W, lin0Wt, 2 * Hh, Hh);
        repack_gatWt_kernel<<<(Hh * Hh) / 256, 256>>>(gat_W, Wgt);
    }

    // 1) poolers (tanh + bias)
    gemm_tc(hidden_cls, nullptr, 64, 32, poolWt, Hh, fea_cls, pooler_b, 1);
    gemm_tc(hidden_emo, nullptr, 64, 32, poolWt, Hh, fea_emo, pooler_b, 1);

    // 2) GAT layer 1
    gemm_tc(fea_cls, nullptr, 64, 32, Wgt, Hh, Wh, nullptr, 0);
    gat_scores_kernel<<<ROWS, 256>>>(Wh, gat_a1, gat_a2, s1, s2);
    mean_rows_kernel<<<dim3(Hh / 256, Bc), 256>>>(Wh, mean1);
    att1_tile_kernel<<<dim3(8, 8, Bc), 128>>>(Wh, s1, s2, h1);
    att1_row0_kernel<<<Bc, 256>>>(mean1, h1);

    // 3) GAT out layer
    gemm_tc(h1, nullptr, 64, 32, outWt, Hh, Wh2, nullptr, 0);
    out_scores_kernel<<<ROWS, 256>>>(Wh2, out_a1, out_a2, s1b, s2b);
    att2_tile_kernel<<<dim3(8, 8, Bc), 128>>>(Wh2, s1b, s2b, h2);

    // 4) row0 swap, lin1, lin0 (K=2048 via split A)
    row0_kernel<<<Bc, 256>>>(fea_cls, h2);
    gemm_tc(h2, nullptr, 64, 32, lin1Wt, Hh, t1, lin1_b, 0);
    gemm_tc(fea_cls, t1, 32, 64, lin0Wt, 2 * Hh, gfin, lin0_b, 0);

    // 5) classifier softmaxes
    cls_softmax_kernel<<<ROWS, 224>>>(gfin, cls_W, cls_b, loggat);
    cls_softmax_kernel<<<ROWS, 224>>>(fea_emo, cls_W, cls_b, Bprob);

    // 6) HMM band filter
    hmm_kernel<<<ROWS / 128, 128>>>(Bprob, hmm_A, loghmm);

    // 7) final logits + loss
    final_kernel<<<ROWS / 256, 256>>>(loggat, loghmm, labels, outLogits);
    finalize_kernel<<<1, 1>>>((float*)d_out, has_loss);
}

// round 5
// speedup vs baseline: 5.3519x; 1.6031x over previous
#include <cuda_runtime.h>
#include <math.h>
#include <stdint.h>

// Problem constants
#define Bc   32
#define Nn   256
#define Hh   1024
#define HEADS 8
#define NHID 128
#define NCLS 7
#define BAND 24
#define ROWS (Bc*Nn)          // 8192
#define ALPHA_LRELU 0.2f

// ---------------- device scratch (no allocs allowed) ----------------
__device__ float g_fea_cls[ROWS*Hh];
__device__ float g_fea_emo[ROWS*Hh];
__device__ float g_Wh[ROWS*Hh];
__device__ float g_h1[ROWS*Hh];
__device__ float g_Wh2[ROWS*Hh];
__device__ float g_h2[ROWS*Hh];
__device__ float g_s1[ROWS*HEADS];
__device__ float g_s2[ROWS*HEADS];
__device__ float g_s1b[ROWS];
__device__ float g_s2b[ROWS];
__device__ float g_mean1[Bc*Hh];
__device__ float g_loggat[ROWS*NCLS];
__device__ float g_Bprob[ROWS*NCLS];
__device__ float g_loghmm[ROWS*NCLS];
__device__ float g_blocksums[32];
// transposed weights ([N][K] K-major, B operand)
__device__ float g_poolWt[Hh*Hh];
__device__ float g_Wgt[Hh*Hh];
__device__ float g_outWt[Hh*Hh];
// folded classifier tables
__device__ float g_U0t[NCLS*Hh];   // [7][1024]: (lin0W_top @ clsW)^T
__device__ float g_U1t[NCLS*Hh];   // [7][1024]: (lin0W_bot @ clsW)^T
__device__ float g_U2t[NCLS*Hh];   // [7][1024]: (lin1W @ U1)^T
__device__ float g_cvec[NCLS];

// =================== mma.sync tf32 GEMM ===================
#define BM 128
#define BN 128
#define BKg 32
#define LDS_PAD 4
#define TILE_LD (BKg + LDS_PAD)              // 36 floats per row
#define STAGE_FLOATS (2 * BM * TILE_LD)      // A + B per stage = 9216
#define GEMM_SMEM (2 * STAGE_FLOATS * 4)     // 73728 bytes

__device__ __forceinline__ uint32_t smem_u32(const void* p) {
    uint32_t a;
    asm("{ .reg .u64 t; cvta.to.shared.u64 t, %1; cvt.u32.u64 %0, t; }" : "=r"(a) : "l"(p));
    return a;
}
__device__ __forceinline__ void cp16(uint32_t s, const void* g) {
    asm volatile("cp.async.cg.shared.global [%0], [%1], 16;" :: "r"(s), "l"(g));
}
#define CP_COMMIT() asm volatile("cp.async.commit_group;" ::: "memory")
#define CP_WAIT0()  asm volatile("cp.async.wait_group 0;" ::: "memory")

// tf32 mma ignores the low 13 bits of each 32-bit operand -> feed raw fp32
// bits (truncation rounding) and skip the cvt.rna in the hot loop.
__device__ __forceinline__ uint32_t f2tf32(float v) { return __float_as_uint(v); }

__device__ __forceinline__ void mma_tf32(float& d0, float& d1, float& d2, float& d3,
                                         uint32_t a0, uint32_t a1, uint32_t a2, uint32_t a3,
                                         uint32_t b0, uint32_t b1) {
    asm volatile("mma.sync.aligned.m16n8k8.row.col.f32.tf32.tf32.f32 "
                 "{%0,%1,%2,%3}, {%4,%5,%6,%7}, {%8,%9}, {%0,%1,%2,%3};"
                 : "+f"(d0), "+f"(d1), "+f"(d2), "+f"(d3)
                 : "r"(a0), "r"(a1), "r"(a2), "r"(a3), "r"(b0), "r"(b1));
}

// stage layout: [stage][ A: BM x TILE_LD | B: BN x TILE_LD ]
__device__ __forceinline__ void gemm_load_stage(uint32_t sb, int stage, int tid,
                                                const float* Ag, const float* Bg, int ldb) {
    uint32_t abase = sb + stage * (STAGE_FLOATS * 4);
    uint32_t bbase = abase + BM * TILE_LD * 4;
#pragma unroll
    for (int i = 0; i < 4; i++) {
        int idx = tid + 256 * i;        // 0..1023
        int r = idx >> 3;               // 0..127
        int q = idx & 7;                // float4 index in 32-float row
        cp16(abase + (r * TILE_LD + q * 4) * 4, Ag + (size_t)r * Hh + q * 4);
        cp16(bbase + (r * TILE_LD + q * 4) * 4, Bg + (size_t)r * ldb + q * 4);
    }
}

__global__ void __launch_bounds__(256, 2)
mma_gemm(const float* __restrict__ A1, const float* __restrict__ A2, int ksplit,
         int T, const float* __restrict__ Bt, int ldb,
         float* __restrict__ C, const float* __restrict__ bias, int dotanh)
{
    extern __shared__ char smem[];
    uint32_t sb = smem_u32(smem);
    float* sbase = (float*)smem;
    const int tid = threadIdx.x;
    const int wid = tid >> 5, lane = tid & 31;
    const int wm = wid >> 2, wn = wid & 3;   // 2x4 warp grid, warp tile 64x32
    const int n0 = blockIdx.x * BN;
    const size_t m0 = (size_t)blockIdx.y * BM;

    float acc[4][4][4];
#pragma unroll
    for (int mi = 0; mi < 4; mi++)
#pragma unroll
        for (int ni = 0; ni < 4; ni++)
#pragma unroll
            for (int k = 0; k < 4; k++) acc[mi][ni][k] = 0.f;

    const float* Brow = Bt + (size_t)n0 * ldb;
    // prologue
    {
        const float* Ag = (0 < ksplit ? A1 : A2) + m0 * Hh;
        gemm_load_stage(sb, 0, tid, Ag, Brow, ldb);
        CP_COMMIT();
    }

    const int lq = lane >> 2;   // 0..7
    const int lr = lane & 3;    // 0..3

    for (int t = 0; t < T; t++) {
        CP_WAIT0();
        __syncthreads();
        // prefetch next stage
        if (t + 1 < T) {
            int nc = t + 1;
            const float* Ag = (nc < ksplit ? A1 + nc * BKg : A2 + (nc - ksplit) * BKg) + m0 * Hh;
            gemm_load_stage(sb, (t + 1) & 1, tid, Ag, Brow + nc * BKg, ldb);
            CP_COMMIT();
        }
        const float* sA = sbase + (t & 1) * STAGE_FLOATS;
        const float* sB = sA + BM * TILE_LD;
#pragma unroll
        for (int kk = 0; kk < BKg; kk += 8) {
            uint32_t af[4][4];
#pragma unroll
            for (int mi = 0; mi < 4; mi++) {
                const float* ap = sA + (wm * 64 + mi * 16 + lq) * TILE_LD + kk + lr;
                af[mi][0] = f2tf32(ap[0]);
                af[mi][1] = f2tf32(ap[8 * TILE_LD]);
                af[mi][2] = f2tf32(ap[4]);
                af[mi][3] = f2tf32(ap[8 * TILE_LD + 4]);
            }
            uint32_t bf[4][2];
#pragma unroll
            for (int ni = 0; ni < 4; ni++) {
                const float* bp = sB + (wn * 32 + ni * 8 + lq) * TILE_LD + kk + lr;
                bf[ni][0] = f2tf32(bp[0]);
                bf[ni][1] = f2tf32(bp[4]);
            }
#pragma unroll
            for (int mi = 0; mi < 4; mi++)
#pragma unroll
                for (int ni = 0; ni < 4; ni++)
                    mma_tf32(acc[mi][ni][0], acc[mi][ni][1], acc[mi][ni][2], acc[mi][ni][3],
                             af[mi][0], af[mi][1], af[mi][2], af[mi][3],
                             bf[ni][0], bf[ni][1]);
        }
        __syncthreads();
    }

    // epilogue
#pragma unroll
    for (int mi = 0; mi < 4; mi++) {
        int row = (int)m0 + wm * 64 + mi * 16 + lq;
#pragma unroll
        for (int ni = 0; ni < 4; ni++) {
            int col = n0 + wn * 32 + ni * 8 + lr * 2;
            float b0 = 0.f, b1 = 0.f;
            if (bias) { b0 = bias[col]; b1 = bias[col + 1]; }
            float2 v0, v1;
            v0.x = acc[mi][ni][0] + b0; v0.y = acc[mi][ni][1] + b1;
            v1.x = acc[mi][ni][2] + b0; v1.y = acc[mi][ni][3] + b1;
            if (dotanh) {
                v0.x = tanhf(v0.x); v0.y = tanhf(v0.y);
                v1.x = tanhf(v1.x); v1.y = tanhf(v1.y);
            }
            *(float2*)(C + (size_t)row * Hh + col) = v0;
            *(float2*)(C + (size_t)(row + 8) * Hh + col) = v1;
        }
    }
}

// =================== weight prep ===================
__global__ void transpose_kernel(const float* __restrict__ in, float* __restrict__ out,
                                 int K, int N)
{
    __shared__ float tile[32][33];
    int k0 = blockIdx.y * 32, n0 = blockIdx.x * 32;
    int tx = threadIdx.x, ty = threadIdx.y;
    for (int r = ty; r < 32; r += 8) tile[r][tx] = in[(size_t)(k0 + r) * N + n0 + tx];
    __syncthreads();
    for (int r = ty; r < 32; r += 8) out[(size_t)(n0 + r) * K + k0 + tx] = tile[tx][r];
}
// Wgt[n=h*128+d][f] = gat_W[h][f][d]
__global__ void repack_gatWt_kernel(const float* __restrict__ gw, float* __restrict__ Wgt)
{
    int idx = blockIdx.x * 256 + threadIdx.x;   // n*1024 + f
    int n = idx >> 10, f = idx & 1023;
    int h = n >> 7, d = n & 127;
    Wgt[idx] = gw[((size_t)(h << 10 | f)) * NHID + d];
}

// U0t[c][r] = sum_k lin0W[r][k]*clsW[k][c]   (r<1024)
// U1t[c][r-1024] likewise for r>=1024. grid 2048 blocks, 224 threads.
__global__ void fold_u_kernel(const float* __restrict__ lin0W,
                              const float* __restrict__ clsW,
                              float* __restrict__ U0t, float* __restrict__ U1t)
{
    int r = blockIdx.x;
    int c = threadIdx.x >> 5, l = threadIdx.x & 31;
    const float* row = lin0W + (size_t)r * Hh;
    float acc = 0.f;
    for (int k = l; k < Hh; k += 32) acc += row[k] * clsW[k * NCLS + c];
    for (int o = 16; o > 0; o >>= 1) acc += __shfl_down_sync(0xffffffffu, acc, o);
    if (l == 0) {
        if (r < Hh) U0t[c * Hh + r] = acc;
        else        U1t[c * Hh + (r - Hh)] = acc;
    }
}

// U2t[c][r] = sum_k lin1W[r][k]*U1t[c][k]. grid 1024 blocks, 224 threads.
__global__ void fold_u2_kernel(const float* __restrict__ lin1W,
                               const float* __restrict__ U1t,
                               float* __restrict__ U2t)
{
    int r = blockIdx.x;
    int c = threadIdx.x >> 5, l = threadIdx.x & 31;
    const float* row = lin1W + (size_t)r * Hh;
    const float* u1 = U1t + c * Hh;
    float acc = 0.f;
    for (int k = l; k < Hh; k += 32) acc += row[k] * u1[k];
    for (int o = 16; o > 0; o >>= 1) acc += __shfl_down_sync(0xffffffffu, acc, o);
    if (l == 0) U2t[c * Hh + r] = acc;
}

// cvec[c] = clsb[c] + lin0b.clsW[:,c] + lin1b.U1t[c]. one block, 224 threads.
__global__ void fold_cvec_kernel(const float* __restrict__ lin0b,
                                 const float* __restrict__ lin1b,
                                 const float* __restrict__ clsW,
                                 const float* __restrict__ clsb,
                                 const float* __restrict__ U1t,
                                 float* __restrict__ cvec)
{
    int c = threadIdx.x >> 5, l = threadIdx.x & 31;
    float acc = 0.f;
    for (int k = l; k < Hh; k += 32)
        acc += lin0b[k] * clsW[k * NCLS + c] + lin1b[k] * U1t[c * Hh + k];
    for (int o = 16; o > 0; o >>= 1) acc += __shfl_down_sync(0xffffffffu, acc, o);
    if (l == 0) cvec[c] = acc + clsb[c];
}

// =================== small kernels ===================
__global__ void gat_scores_kernel(const float* __restrict__ Wh,
                                  const float* __restrict__ a1,
                                  const float* __restrict__ a2,
                                  float* __restrict__ s1, float* __restrict__ s2)
{
    int n = blockIdx.x;
    int w = threadIdx.x >> 5, l = threadIdx.x & 31;
    const float* row = Wh + (size_t)n * Hh + w * NHID;
    float x1 = 0.f, x2 = 0.f;
#pragma unroll
    for (int t = 0; t < 4; t++) {
        float v = row[l + 32 * t];
        x1 += v * a1[w * NHID + l + 32 * t];
        x2 += v * a2[w * NHID + l + 32 * t];
    }
    for (int o = 16; o > 0; o >>= 1) {
        x1 += __shfl_down_sync(0xffffffffu, x1, o);
        x2 += __shfl_down_sync(0xffffffffu, x2, o);
    }
    if (l == 0) { s1[n * HEADS + w] = x1; s2[n * HEADS + w] = x2; }
}

__global__ void mean_rows_kernel(const float* __restrict__ X, float* __restrict__ out)
{
    int b = blockIdx.y;
    int c = blockIdx.x * 256 + threadIdx.x;
    const float* p = X + (size_t)b * Nn * Hh + c;
    float s = 0.f;
    for (int n = 0; n < Nn; n++) s += p[(size_t)n * Hh];
    out[b * Hh + c] = s * (1.0f / Nn);
}

__device__ __forceinline__ float eluf(float x) { return x > 0.f ? x : expf(x) - 1.0f; }

// tiled band attention, layer 1 (per-head). grid(8 i-tiles, 8 heads, 32 batches), 128 thr
__global__ void att1_tile_kernel(const float* __restrict__ Wh,
                                 const float* __restrict__ s1,
                                 const float* __restrict__ s2,
                                 float* __restrict__ h1)
{
    __shared__ float sW[54][128];
    __shared__ float sw[32][24];
    int b = blockIdx.z, h = blockIdx.y, it = blockIdx.x;
    int i0 = it * 32;
    int jlo0 = i0 - 23; if (jlo0 < 0) jlo0 = 0;
    int nrows = (i0 + 30) - jlo0 + 1;
    int tid = threadIdx.x;
    const float* base = Wh + (size_t)b * Nn * Hh + h * NHID;
    for (int rr = 0; rr < nrows; rr++)
        sW[rr][tid] = base[(size_t)(jlo0 + rr) * Hh + tid];
    if (tid < 32) {
        int i = i0 + tid;
        if (i > 0) {
            int jl = i - 23; if (jl < 0) jl = 0;
            int L = i - jl;
            float si = s1[((size_t)b * Nn + i) * HEADS + h];
            float mx = -1e30f;
            for (int t = 0; t < L; t++) {
                float v = si + s2[((size_t)b * Nn + jl + t) * HEADS + h];
                v = v > 0.f ? v : ALPHA_LRELU * v;
                sw[tid][t] = v; mx = fmaxf(mx, v);
            }
            float ssum = 0.f;
            for (int t = 0; t < L; t++) { float ex = expf(sw[tid][t] - mx); sw[tid][t] = ex; ssum += ex; }
            float inv = 1.0f / ssum;
            for (int t = 0; t < L; t++) sw[tid][t] *= inv;
        }
    }
    __syncthreads();
    for (int il = 0; il < 32; il++) {
        int i = i0 + il;
        if (i == 0) continue;
        int jl = i - 23; if (jl < 0) jl = 0;
        int L = i - jl, roff = jl - jlo0;
        float acc = 0.f;
        for (int t = 0; t < L; t++) acc += sw[il][t] * sW[roff + t][tid];
        h1[((size_t)b * Nn + i) * Hh + h * NHID + tid] = eluf(acc);
    }
}

// row 0 of h1 = elu(mean over rows of Wh)
__global__ void att1_row0_kernel(const float* __restrict__ mean1, float* __restrict__ h1)
{
    int b = blockIdx.x;
    for (int c = threadIdx.x; c < Hh; c += 256)
        h1[(size_t)b * Nn * Hh + c] = eluf(mean1[b * Hh + c]);
}

__global__ void out_scores_kernel(const float* __restrict__ Wh2,
                                  const float* __restrict__ a1,
                                  const float* __restrict__ a2,
                                  float* __restrict__ s1, float* __restrict__ s2)
{
    int n = blockIdx.x;
    int tid = threadIdx.x;
    float x1 = 0.f, x2 = 0.f;
    const float* x = Wh2 + (size_t)n * Hh;
    for (int c = tid; c < Hh; c += 256) { float v = x[c]; x1 += v * a1[c]; x2 += v * a2[c]; }
    __shared__ float sh1[8], sh2[8];
    for (int o = 16; o > 0; o >>= 1) {
        x1 += __shfl_down_sync(0xffffffffu, x1, o);
        x2 += __shfl_down_sync(0xffffffffu, x2, o);
    }
    if ((tid & 31) == 0) { sh1[tid >> 5] = x1; sh2[tid >> 5] = x2; }
    __syncthreads();
    if (tid == 0) {
        float t1 = 0.f, t2 = 0.f;
        for (int k = 0; k < 8; k++) { t1 += sh1[k]; t2 += sh2[k]; }
        s1[n] = t1; s2[n] = t2;
    }
}

// tiled band attention, out layer. grid(8 i-tiles, 8 col-tiles, 32 batches), 128 thr
__global__ void att2_tile_kernel(const float* __restrict__ Wh2,
                                 const float* __restrict__ s1,
                                 const float* __restrict__ s2,
                                 float* __restrict__ out)
{
    __shared__ float sW[54][128];
    __shared__ float sw[32][24];
    int b = blockIdx.z, ct = blockIdx.y, it = blockIdx.x;
    int i0 = it * 32, c0 = ct * 128;
    int jlo0 = i0 - 23; if (jlo0 < 0) jlo0 = 0;
    int nrows = (i0 + 30) - jlo0 + 1;
    int tid = threadIdx.x;
    const float* base = Wh2 + (size_t)b * Nn * Hh + c0;
    for (int rr = 0; rr < nrows; rr++)
        sW[rr][tid] = base[(size_t)(jlo0 + rr) * Hh + tid];
    if (tid < 32) {
        int i = i0 + tid;
        if (i > 0) {
            int jl = i - 23; if (jl < 0) jl = 0;
            int L = i - jl;
            float si = s1[(size_t)b * Nn + i];
            float mx = -1e30f;
            for (int t = 0; t < L; t++) {
                float v = si + s2[(size_t)b * Nn + jl + t];
                v = v > 0.f ? v : ALPHA_LRELU * v;
                sw[tid][t] = v; mx = fmaxf(mx, v);
            }
            float ssum = 0.f;
            for (int t = 0; t < L; t++) { float ex = expf(sw[tid][t] - mx); sw[tid][t] = ex; ssum += ex; }
            float inv = 1.0f / ssum;
            for (int t = 0; t < L; t++) sw[tid][t] *= inv;
        }
    }
    __syncthreads();
    for (int il = 0; il < 32; il++) {
        int i = i0 + il;
        if (i == 0) continue;
        int jl = i - 23; if (jl < 0) jl = 0;
        int L = i - jl, roff = jl - jlo0;
        float acc = 0.f;
        for (int t = 0; t < L; t++) acc += sw[il][t] * sW[roff + t][tid];
        out[((size_t)b * Nn + i) * Hh + c0 + tid] = eluf(acc);
    }
}

// fused GAT logits: loggat[n] = softmax_c( fea_cls[n].U0t[c] + hrow.U2t[c] + cvec[c] )
// hrow = h2[n] except i==0 where hrow = fea_cls[n]. 8192 blocks x 224 threads.
__global__ void gat_logits_kernel(const float* __restrict__ fea_cls,
                                  const float* __restrict__ h2,
                                  const float* __restrict__ U0t,
                                  const float* __restrict__ U2t,
                                  const float* __restrict__ cvec,
                                  float* __restrict__ out)
{
    int n = blockIdx.x;
    int i = n & (Nn - 1);
    int c = threadIdx.x >> 5, l = threadIdx.x & 31;
    const float* frow = fea_cls + (size_t)n * Hh;
    const float* hrow = (i == 0) ? frow : h2 + (size_t)n * Hh;
    const float* u0 = U0t + c * Hh;
    const float* u2 = U2t + c * Hh;
    float acc = 0.f;
    for (int k = l; k < Hh; k += 32)
        acc += frow[k] * u0[k] + hrow[k] * u2[k];
    for (int o = 16; o > 0; o >>= 1) acc += __shfl_down_sync(0xffffffffu, acc, o);
    __shared__ float sh[NCLS];
    if (l == 0) sh[c] = acc + cvec[c];
    __syncthreads();
    if (threadIdx.x == 0) {
        float mx = sh[0];
        for (int k = 1; k < NCLS; k++) mx = fmaxf(mx, sh[k]);
        float e[NCLS], s = 0.f;
        for (int k = 0; k < NCLS; k++) { e[k] = expf(sh[k] - mx); s += e[k]; }
        float inv = 1.0f / s;
        for (int k = 0; k < NCLS; k++) out[n * NCLS + k] = e[k] * inv;
    }
}

__global__ void cls_softmax_kernel(const float* __restrict__ X,
                                   const float* __restrict__ W,
                                   const float* __restrict__ bcls,
                                   float* __restrict__ out)
{
    int n = blockIdx.x;
    int wid = threadIdx.x >> 5, l = threadIdx.x & 31;
    __shared__ float sh[NCLS];
    const float* x = X + (size_t)n * Hh;
    float acc = 0.f;
    for (int t = l; t < Hh; t += 32) acc += x[t] * W[t * NCLS + wid];
    for (int o = 16; o > 0; o >>= 1) acc += __shfl_down_sync(0xffffffffu, acc, o);
    if (l == 0) sh[wid] = acc + bcls[wid];
    __syncthreads();
    if (threadIdx.x == 0) {
        float mx = sh[0];
        for (int k = 1; k < NCLS; k++) mx = fmaxf(mx, sh[k]);
        float e[NCLS], s = 0.f;
        for (int k = 0; k < NCLS; k++) { e[k] = expf(sh[k] - mx); s += e[k]; }
        float inv = 1.0f / s;
        for (int k = 0; k < NCLS; k++) out[n * NCLS + k] = e[k] * inv;
    }
}

__global__ void hmm_kernel(const float* __restrict__ Bprob,
                           const float* __restrict__ hmmA,
                           float* __restrict__ out)
{
    __shared__ float sAT[NCLS * NCLS];
    int tid = threadIdx.x;
    if (tid < NCLS * NCLS) sAT[tid] = hmmA[(tid % NCLS) * NCLS + (tid / NCLS)];
    __syncthreads();
    int gidx = blockIdx.x * 128 + tid;
    int b = gidx >> 8, i = gidx & 255;
    const float* Bp = Bprob + (size_t)b * Nn * NCLS;
    int t0 = i - (BAND - 1); if (t0 < 0) t0 = 0;
    float p[NCLS]; float s = 0.f;
#pragma unroll
    for (int r = 0; r < NCLS; r++) { p[r] = Bp[t0 * NCLS + r]; s += p[r]; }
    float inv = 1.0f / s;
#pragma unroll
    for (int r = 0; r < NCLS; r++) p[r] *= inv;
    for (int t = t0 + 1; t <= i; t++) {
        float q[NCLS]; s = 0.f;
#pragma unroll
        for (int r = 0; r < NCLS; r++) {
            float a = 0.f;
#pragma unroll
            for (int c = 0; c < NCLS; c++) a += sAT[r * NCLS + c] * p[c];
            a *= Bp[t * NCLS + r];
            q[r] = a; s += a;
        }
        inv = 1.0f / s;
#pragma unroll
        for (int r = 0; r < NCLS; r++) p[r] = q[r] * inv;
    }
#pragma unroll
    for (int r = 0; r < NCLS; r++) out[gidx * NCLS + r] = p[r];
}

__global__ void final_kernel(const float* __restrict__ log_gat,
                             const float* __restrict__ log_hmm,
                             const int* __restrict__ labels,
                             float* __restrict__ outLogits)
{
    int r = blockIdx.x * 256 + threadIdx.x;
    float lg[NCLS];
#pragma unroll
    for (int k = 0; k < NCLS; k++) {
        lg[k] = logf(0.5f * (log_gat[r * NCLS + k] + log_hmm[r * NCLS + k]));
        outLogits[r * NCLS + k] = lg[k];
    }
    int lab = labels[r];
    float picked = (lab >= 0) ? lg[lab] : 0.f;
    for (int o = 16; o > 0; o >>= 1) picked += __shfl_down_sync(0xffffffffu, picked, o);
    __shared__ float sh[8];
    if ((threadIdx.x & 31) == 0) sh[threadIdx.x >> 5] = picked;
    __syncthreads();
    if (threadIdx.x == 0) {
        float s = 0.f;
        for (int k = 0; k < 8; k++) s += sh[k];
        g_blocksums[blockIdx.x] = s;
    }
}

__global__ void finalize_kernel(float* d_out, int has_loss)
{
    if (has_loss) {
        float s = 0.f;
        for (int k = 0; k < 32; k++) s += g_blocksums[k];
        d_out[0] = -s / (float)ROWS;
    }
}

// ---------------- host launch ----------------
template <typename T>
static T* sym(const void* symbol)
{
    void* p = nullptr;
    cudaGetSymbolAddress(&p, symbol);
    return (T*)p;
}

static void gemm_tc(const float* A1, const float* A2, int ksplit, int T,
                    const float* Bt, int ldb, float* C, const float* bias, int dotanh)
{
    dim3 grid(Hh / BN, ROWS / BM);
    mma_gemm<<<grid, 256, GEMM_SMEM>>>(A1, A2, ksplit, T, Bt, ldb, C, bias, dotanh);
}

extern "C" void kernel_launch(void* const* d_in, const int* in_sizes, int n_in,
                              void* d_out, int out_size)
{
    (void)in_sizes; (void)n_in;
    const float* hidden_cls = (const float*)d_in[0];
    const float* hidden_emo = (const float*)d_in[1];
    const int*   labels     = (const int*)d_in[3];
    const float* pooler_W   = (const float*)d_in[4];
    const float* pooler_b   = (const float*)d_in[5];
    const float* gat_W      = (const float*)d_in[6];
    const float* gat_a1     = (const float*)d_in[7];
    const float* gat_a2     = (const float*)d_in[8];
    const float* out_W      = (const float*)d_in[9];
    const float* out_a1     = (const float*)d_in[10];
    const float* out_a2     = (const float*)d_in[11];
    const float* lin1_W     = (const float*)d_in[12];
    const float* lin1_b     = (const float*)d_in[13];
    const float* lin0_W     = (const float*)d_in[14];
    const float* lin0_b     = (const float*)d_in[15];
    const float* cls_W      = (const float*)d_in[16];
    const float* cls_b      = (const float*)d_in[17];
    const float* hmm_A      = (const float*)d_in[18];

    float* fea_cls = sym<float>(g_fea_cls);
    float* fea_emo = sym<float>(g_fea_emo);
    float* Wh      = sym<float>(g_Wh);
    float* h1      = sym<float>(g_h1);
    float* Wh2     = sym<float>(g_Wh2);
    float* h2      = sym<float>(g_h2);
    float* s1      = sym<float>(g_s1);
    float* s2      = sym<float>(g_s2);
    float* s1b     = sym<float>(g_s1b);
    float* s2b     = sym<float>(g_s2b);
    float* mean1   = sym<float>(g_mean1);
    float* loggat  = sym<float>(g_loggat);
    float* Bprob   = sym<float>(g_Bprob);
    float* loghmm  = sym<float>(g_loghmm);
    float* poolWt  = sym<float>(g_poolWt);
    float* Wgt     = sym<float>(g_Wgt);
    float* outWt   = sym<float>(g_outWt);
    float* U0t     = sym<float>(g_U0t);
    float* U1t     = sym<float>(g_U1t);
    float* U2t     = sym<float>(g_U2t);
    float* cvec    = sym<float>(g_cvec);

    cudaFuncSetAttribute(mma_gemm, cudaFuncAttributeMaxDynamicSharedMemorySize, GEMM_SMEM);

    int has_loss = (out_size == ROWS * NCLS + 1) ? 1 : 0;
    float* outLogits = has_loss ? ((float*)d_out + 1) : (float*)d_out;

    // 0) weight prep + classifier folding
    {
        dim3 blk(32, 8);
        transpose_kernel<<<dim3(Hh / 32, Hh / 32), blk>>>(pooler_W, poolWt, Hh, Hh);
        transpose_kernel<<<dim3(Hh / 32, Hh / 32), blk>>>(out_W, outWt, Hh, Hh);
        repack_gatWt_kernel<<<(Hh * Hh) / 256, 256>>>(gat_W, Wgt);
        fold_u_kernel<<<2 * Hh, 224>>>(lin0_W, cls_W, U0t, U1t);
        fold_u2_kernel<<<Hh, 224>>>(lin1_W, U1t, U2t);
        fold_cvec_kernel<<<1, 224>>>(lin0_b, lin1_b, cls_W, cls_b, U1t, cvec);
    }

    // 1) poolers (tanh + bias)
    gemm_tc(hidden_cls, nullptr, 64, 32, poolWt, Hh, fea_cls, pooler_b, 1);
    gemm_tc(hidden_emo, nullptr, 64, 32, poolWt, Hh, fea_emo, pooler_b, 1);

    // 2) GAT layer 1
    gemm_tc(fea_cls, nullptr, 64, 32, Wgt, Hh, Wh, nullptr, 0);
    gat_scores_kernel<<<ROWS, 256>>>(Wh, gat_a1, gat_a2, s1, s2);
    mean_rows_kernel<<<dim3(Hh / 256, Bc), 256>>>(Wh, mean1);
    att1_tile_kernel<<<dim3(8, 8, Bc), 128>>>(Wh, s1, s2, h1);
    att1_row0_kernel<<<Bc, 256>>>(mean1, h1);

    // 3) GAT out layer
    gemm_tc(h1, nullptr, 64, 32, outWt, Hh, Wh2, nullptr, 0);
    out_scores_kernel<<<ROWS, 256>>>(Wh2, out_a1, out_a2, s1b, s2b);
    att2_tile_kernel<<<dim3(8, 8, Bc), 128>>>(Wh2, s1b, s2b, h2);

    // 4) folded classifier head (lin1+lin0+cls collapsed into U0/U2/cvec)
    gat_logits_kernel<<<ROWS, 224>>>(fea_cls, h2, U0t, U2t, cvec, loggat);

    // 5) HMM emission probs
    cls_softmax_kernel<<<ROWS, 224>>>(fea_emo, cls_W, cls_b, Bprob);

    // 6) HMM band filter
    hmm_kernel<<<ROWS / 128, 128>>>(Bprob, hmm_A, loghmm);

    // 7) final logits + loss
    final_kernel<<<ROWS / 256, 256>>>(loggat, loghmm, labels, outLogits);
    finalize_kernel<<<1, 1>>>((float*)d_out, has_loss);
}

// round 6
// speedup vs baseline: 5.6318x; 1.0523x over previous
#include <cuda_runtime.h>
#include <math.h>
#include <stdint.h>

// Problem constants
#define Bc   32
#define Nn   256
#define Hh   1024
#define HEADS 8
#define NHID 128
#define NCLS 7
#define BAND 24
#define ROWS (Bc*Nn)          // 8192
#define ALPHA_LRELU 0.2f

// ---------------- device scratch (no allocs allowed) ----------------
__device__ float g_fea_cls[ROWS*Hh];
__device__ float g_fea_emo[ROWS*Hh];
__device__ float g_Wh[ROWS*Hh];
__device__ float g_h1[ROWS*Hh];
__device__ float g_Wh2[ROWS*Hh];
__device__ float g_h2[ROWS*Hh];
__device__ float g_s1[ROWS*HEADS];
__device__ float g_s2[ROWS*HEADS];
__device__ float g_s1b[ROWS];
__device__ float g_s2b[ROWS];
__device__ float g_mean1[Bc*Hh];
__device__ float g_loggat[ROWS*NCLS];
__device__ float g_Bprob[ROWS*NCLS];
__device__ float g_loghmm[ROWS*NCLS];
__device__ float g_blocksums[32];
// transposed weights ([N][K] K-major, B operand)
__device__ float g_poolWt[Hh*Hh];
__device__ float g_Wgt[Hh*Hh];
__device__ float g_outWt[Hh*Hh];
// folded classifier tables
__device__ float g_U0t[NCLS*Hh];
__device__ float g_U1t[NCLS*Hh];
__device__ float g_U2t[NCLS*Hh];
__device__ float g_cvec[NCLS];

// =================== mma.sync tf32 GEMM (3-stage pipeline) ===================
#define BM 128
#define BN 128
#define BKg 32
#define GSTG 3
#define LDS_PAD 4
#define TILE_LD (BKg + LDS_PAD)              // 36 floats per row
#define STAGE_FLOATS (2 * BM * TILE_LD)      // A + B per stage = 9216 floats
#define GEMM_SMEM (GSTG * STAGE_FLOATS * 4)  // 110592 bytes

__device__ __forceinline__ uint32_t smem_u32(const void* p) {
    uint32_t a;
    asm("{ .reg .u64 t; cvta.to.shared.u64 t, %1; cvt.u32.u64 %0, t; }" : "=r"(a) : "l"(p));
    return a;
}
__device__ __forceinline__ void cp16(uint32_t s, const void* g) {
    asm volatile("cp.async.cg.shared.global [%0], [%1], 16;" :: "r"(s), "l"(g));
}
#define CP_COMMIT() asm volatile("cp.async.commit_group;" ::: "memory")
#define CP_WAIT1()  asm volatile("cp.async.wait_group 1;" ::: "memory")

// tf32 mma ignores the low 13 bits -> raw fp32 bits (truncation rounding).
__device__ __forceinline__ uint32_t f2tf32(float v) { return __float_as_uint(v); }

__device__ __forceinline__ void mma_tf32(float& d0, float& d1, float& d2, float& d3,
                                         uint32_t a0, uint32_t a1, uint32_t a2, uint32_t a3,
                                         uint32_t b0, uint32_t b1) {
    asm volatile("mma.sync.aligned.m16n8k8.row.col.f32.tf32.tf32.f32 "
                 "{%0,%1,%2,%3}, {%4,%5,%6,%7}, {%8,%9}, {%0,%1,%2,%3};"
                 : "+f"(d0), "+f"(d1), "+f"(d2), "+f"(d3)
                 : "r"(a0), "r"(a1), "r"(a2), "r"(a3), "r"(b0), "r"(b1));
}

// stage layout: [stage][ A: BM x TILE_LD | B: BN x TILE_LD ]
__device__ __forceinline__ void gemm_load_stage(uint32_t sb, int stage, int tid,
                                                const float* Ag, const float* Bg) {
    uint32_t abase = sb + stage * (STAGE_FLOATS * 4);
    uint32_t bbase = abase + BM * TILE_LD * 4;
#pragma unroll
    for (int i = 0; i < 4; i++) {
        int idx = tid + 256 * i;        // 0..1023
        int r = idx >> 3;               // 0..127
        int q = idx & 7;                // float4 index in 32-float row
        cp16(abase + (r * TILE_LD + q * 4) * 4, Ag + (size_t)r * Hh + q * 4);
        cp16(bbase + (r * TILE_LD + q * 4) * 4, Bg + (size_t)r * Hh + q * 4);
    }
}

// z-batched: blockIdx.z selects (Aa,Ca) or (Ab,Cb). B shared. ld == Hh.
__global__ void __launch_bounds__(256, 2)
mma_gemm(const float* __restrict__ Aa, const float* __restrict__ Ab,
         float* __restrict__ Ca, float* __restrict__ Cb,
         const float* __restrict__ Bt,
         const float* __restrict__ bias, int dotanh, int T)
{
    extern __shared__ char smem[];
    uint32_t sb = smem_u32(smem);
    float* sbase = (float*)smem;
    const int tid = threadIdx.x;
    const int wid = tid >> 5, lane = tid & 31;
    const int wm = wid >> 2, wn = wid & 3;   // 2x4 warp grid, warp tile 64x32
    const int n0 = blockIdx.x * BN;
    const size_t m0 = (size_t)blockIdx.y * BM;
    const float* A = (blockIdx.z == 0) ? Aa : Ab;
    float* C = (blockIdx.z == 0) ? Ca : Cb;

    float acc[4][4][4];
#pragma unroll
    for (int mi = 0; mi < 4; mi++)
#pragma unroll
        for (int ni = 0; ni < 4; ni++)
#pragma unroll
            for (int k = 0; k < 4; k++) acc[mi][ni][k] = 0.f;

    const float* Arow = A + m0 * Hh;
    const float* Brow = Bt + (size_t)n0 * Hh;

    // prologue: stages 0 and 1
    gemm_load_stage(sb, 0, tid, Arow, Brow);
    CP_COMMIT();
    gemm_load_stage(sb, 1, tid, Arow + BKg, Brow + BKg);
    CP_COMMIT();

    const int lq = lane >> 2;   // 0..7
    const int lr = lane & 3;    // 0..3

    for (int t = 0; t < T; t++) {
        CP_WAIT1();             // stage t resident (newest group may be in flight)
        __syncthreads();        // also protects slot reuse: compute(t-1) done on all threads
        int nc = t + 2;
        if (nc < T)
            gemm_load_stage(sb, nc % GSTG, tid, Arow + nc * BKg, Brow + nc * BKg);
        CP_COMMIT();            // always commit (possibly empty) to keep group counting sound

        const float* sA = sbase + (t % GSTG) * STAGE_FLOATS;
        const float* sB = sA + BM * TILE_LD;
#pragma unroll
        for (int kk = 0; kk < BKg; kk += 8) {
            uint32_t af[4][4];
#pragma unroll
            for (int mi = 0; mi < 4; mi++) {
                const float* ap = sA + (wm * 64 + mi * 16 + lq) * TILE_LD + kk + lr;
                af[mi][0] = f2tf32(ap[0]);
                af[mi][1] = f2tf32(ap[8 * TILE_LD]);
                af[mi][2] = f2tf32(ap[4]);
                af[mi][3] = f2tf32(ap[8 * TILE_LD + 4]);
            }
            uint32_t bf[4][2];
#pragma unroll
            for (int ni = 0; ni < 4; ni++) {
                const float* bp = sB + (wn * 32 + ni * 8 + lq) * TILE_LD + kk + lr;
                bf[ni][0] = f2tf32(bp[0]);
                bf[ni][1] = f2tf32(bp[4]);
            }
#pragma unroll
            for (int mi = 0; mi < 4; mi++)
#pragma unroll
                for (int ni = 0; ni < 4; ni++)
                    mma_tf32(acc[mi][ni][0], acc[mi][ni][1], acc[mi][ni][2], acc[mi][ni][3],
                             af[mi][0], af[mi][1], af[mi][2], af[mi][3],
                             bf[ni][0], bf[ni][1]);
        }
    }

    // epilogue
#pragma unroll
    for (int mi = 0; mi < 4; mi++) {
        int row = (int)m0 + wm * 64 + mi * 16 + lq;
#pragma unroll
        for (int ni = 0; ni < 4; ni++) {
            int col = n0 + wn * 32 + ni * 8 + lr * 2;
            float b0 = 0.f, b1 = 0.f;
            if (bias) { b0 = bias[col]; b1 = bias[col + 1]; }
            float2 v0, v1;
            v0.x = acc[mi][ni][0] + b0; v0.y = acc[mi][ni][1] + b1;
            v1.x = acc[mi][ni][2] + b0; v1.y = acc[mi][ni][3] + b1;
            if (dotanh) {
                v0.x = tanhf(v0.x); v0.y = tanhf(v0.y);
                v1.x = tanhf(v1.x); v1.y = tanhf(v1.y);
            }
            *(float2*)(C + (size_t)row * Hh + col) = v0;
            *(float2*)(C + (size_t)(row + 8) * Hh + col) = v1;
        }
    }
}

// =================== weight prep ===================
__global__ void transpose_kernel(const float* __restrict__ in, float* __restrict__ out,
                                 int K, int N)
{
    __shared__ float tile[32][33];
    int k0 = blockIdx.y * 32, n0 = blockIdx.x * 32;
    int tx = threadIdx.x, ty = threadIdx.y;
    for (int r = ty; r < 32; r += 8) tile[r][tx] = in[(size_t)(k0 + r) * N + n0 + tx];
    __syncthreads();
    for (int r = ty; r < 32; r += 8) out[(size_t)(n0 + r) * K + k0 + tx] = tile[tx][r];
}
__global__ void repack_gatWt_kernel(const float* __restrict__ gw, float* __restrict__ Wgt)
{
    int idx = blockIdx.x * 256 + threadIdx.x;   // n*1024 + f
    int n = idx >> 10, f = idx & 1023;
    int h = n >> 7, d = n & 127;
    Wgt[idx] = gw[((size_t)(h << 10 | f)) * NHID + d];
}

__global__ void fold_u_kernel(const float* __restrict__ lin0W,
                              const float* __restrict__ clsW,
                              float* __restrict__ U0t, float* __restrict__ U1t)
{
    int r = blockIdx.x;
    int c = threadIdx.x >> 5, l = threadIdx.x & 31;
    const float* row = lin0W + (size_t)r * Hh;
    float acc = 0.f;
    for (int k = l; k < Hh; k += 32) acc += row[k] * clsW[k * NCLS + c];
    for (int o = 16; o > 0; o >>= 1) acc += __shfl_down_sync(0xffffffffu, acc, o);
    if (l == 0) {
        if (r < Hh) U0t[c * Hh + r] = acc;
        else        U1t[c * Hh + (r - Hh)] = acc;
    }
}

__global__ void fold_u2_kernel(const float* __restrict__ lin1W,
                               const float* __restrict__ U1t,
                               float* __restrict__ U2t)
{
    int r = blockIdx.x;
    int c = threadIdx.x >> 5, l = threadIdx.x & 31;
    const float* row = lin1W + (size_t)r * Hh;
    const float* u1 = U1t + c * Hh;
    float acc = 0.f;
    for (int k = l; k < Hh; k += 32) acc += row[k] * u1[k];
    for (int o = 16; o > 0; o >>= 1) acc += __shfl_down_sync(0xffffffffu, acc, o);
    if (l == 0) U2t[c * Hh + r] = acc;
}

__global__ void fold_cvec_kernel(const float* __restrict__ lin0b,
                                 const float* __restrict__ lin1b,
                                 const float* __restrict__ clsW,
                                 const float* __restrict__ clsb,
                                 const float* __restrict__ U1t,
                                 float* __restrict__ cvec)
{
    int c = threadIdx.x >> 5, l = threadIdx.x & 31;
    float acc = 0.f;
    for (int k = l; k < Hh; k += 32)
        acc += lin0b[k] * clsW[k * NCLS + c] + lin1b[k] * U1t[c * Hh + k];
    for (int o = 16; o > 0; o >>= 1) acc += __shfl_down_sync(0xffffffffu, acc, o);
    if (l == 0) cvec[c] = acc + clsb[c];
}

// =================== small kernels ===================
__global__ void gat_scores_kernel(const float* __restrict__ Wh,
                                  const float* __restrict__ a1,
                                  const float* __restrict__ a2,
                                  float* __restrict__ s1, float* __restrict__ s2)
{
    int n = blockIdx.x;
    int w = threadIdx.x >> 5, l = threadIdx.x & 31;
    const float* row = Wh + (size_t)n * Hh + w * NHID;
    float x1 = 0.f, x2 = 0.f;
#pragma unroll
    for (int t = 0; t < 4; t++) {
        float v = row[l + 32 * t];
        x1 += v * a1[w * NHID + l + 32 * t];
        x2 += v * a2[w * NHID + l + 32 * t];
    }
    for (int o = 16; o > 0; o >>= 1) {
        x1 += __shfl_down_sync(0xffffffffu, x1, o);
        x2 += __shfl_down_sync(0xffffffffu, x2, o);
    }
    if (l == 0) { s1[n * HEADS + w] = x1; s2[n * HEADS + w] = x2; }
}

__global__ void mean_rows_kernel(const float* __restrict__ X, float* __restrict__ out)
{
    int b = blockIdx.y;
    int c = blockIdx.x * 256 + threadIdx.x;
    const float* p = X + (size_t)b * Nn * Hh + c;
    float s = 0.f;
    for (int n = 0; n < Nn; n++) s += p[(size_t)n * Hh];
    out[b * Hh + c] = s * (1.0f / Nn);
}

__device__ __forceinline__ float eluf(float x) { return x > 0.f ? x : expf(x) - 1.0f; }

__global__ void att1_tile_kernel(const float* __restrict__ Wh,
                                 const float* __restrict__ s1,
                                 const float* __restrict__ s2,
                                 float* __restrict__ h1)
{
    __shared__ float sW[54][128];
    __shared__ float sw[32][24];
    int b = blockIdx.z, h = blockIdx.y, it = blockIdx.x;
    int i0 = it * 32;
    int jlo0 = i0 - 23; if (jlo0 < 0) jlo0 = 0;
    int nrows = (i0 + 30) - jlo0 + 1;
    int tid = threadIdx.x;
    const float* base = Wh + (size_t)b * Nn * Hh + h * NHID;
    for (int rr = 0; rr < nrows; rr++)
        sW[rr][tid] = base[(size_t)(jlo0 + rr) * Hh + tid];
    if (tid < 32) {
        int i = i0 + tid;
        if (i > 0) {
            int jl = i - 23; if (jl < 0) jl = 0;
            int L = i - jl;
            float si = s1[((size_t)b * Nn + i) * HEADS + h];
            float mx = -1e30f;
            for (int t = 0; t < L; t++) {
                float v = si + s2[((size_t)b * Nn + jl + t) * HEADS + h];
                v = v > 0.f ? v : ALPHA_LRELU * v;
                sw[tid][t] = v; mx = fmaxf(mx, v);
            }
            float ssum = 0.f;
            for (int t = 0; t < L; t++) { float ex = expf(sw[tid][t] - mx); sw[tid][t] = ex; ssum += ex; }
            float inv = 1.0f / ssum;
            for (int t = 0; t < L; t++) sw[tid][t] *= inv;
        }
    }
    __syncthreads();
    for (int il = 0; il < 32; il++) {
        int i = i0 + il;
        if (i == 0) continue;
        int jl = i - 23; if (jl < 0) jl = 0;
        int L = i - jl, roff = jl - jlo0;
        float acc = 0.f;
        for (int t = 0; t < L; t++) acc += sw[il][t] * sW[roff + t][tid];
        h1[((size_t)b * Nn + i) * Hh + h * NHID + tid] = eluf(acc);
    }
}

__global__ void att1_row0_kernel(const float* __restrict__ mean1, float* __restrict__ h1)
{
    int b = blockIdx.x;
    for (int c = threadIdx.x; c < Hh; c += 256)
        h1[(size_t)b * Nn * Hh + c] = eluf(mean1[b * Hh + c]);
}

__global__ void out_scores_kernel(const float* __restrict__ Wh2,
                                  const float* __restrict__ a1,
                                  const float* __restrict__ a2,
                                  float* __restrict__ s1, float* __restrict__ s2)
{
    int n = blockIdx.x;
    int tid = threadIdx.x;
    float x1 = 0.f, x2 = 0.f;
    const float* x = Wh2 + (size_t)n * Hh;
    for (int c = tid; c < Hh; c += 256) { float v = x[c]; x1 += v * a1[c]; x2 += v * a2[c]; }
    __shared__ float sh1[8], sh2[8];
    for (int o = 16; o > 0; o >>= 1) {
        x1 += __shfl_down_sync(0xffffffffu, x1, o);
        x2 += __shfl_down_sync(0xffffffffu, x2, o);
    }
    if ((tid & 31) == 0) { sh1[tid >> 5] = x1; sh2[tid >> 5] = x2; }
    __syncthreads();
    if (tid == 0) {
        float t1 = 0.f, t2 = 0.f;
        for (int k = 0; k < 8; k++) { t1 += sh1[k]; t2 += sh2[k]; }
        s1[n] = t1; s2[n] = t2;
    }
}

__global__ void att2_tile_kernel(const float* __restrict__ Wh2,
                                 const float* __restrict__ s1,
                                 const float* __restrict__ s2,
                                 float* __restrict__ out)
{
    __shared__ float sW[54][128];
    __shared__ float sw[32][24];
    int b = blockIdx.z, ct = blockIdx.y, it = blockIdx.x;
    int i0 = it * 32, c0 = ct * 128;
    int jlo0 = i0 - 23; if (jlo0 < 0) jlo0 = 0;
    int nrows = (i0 + 30) - jlo0 + 1;
    int tid = threadIdx.x;
    const float* base = Wh2 + (size_t)b * Nn * Hh + c0;
    for (int rr = 0; rr < nrows; rr++)
        sW[rr][tid] = base[(size_t)(jlo0 + rr) * Hh + tid];
    if (tid < 32) {
        int i = i0 + tid;
        if (i > 0) {
            int jl = i - 23; if (jl < 0) jl = 0;
            int L = i - jl;
            float si = s1[(size_t)b * Nn + i];
            float mx = -1e30f;
            for (int t = 0; t < L; t++) {
                float v = si + s2[(size_t)b * Nn + jl + t];
                v = v > 0.f ? v : ALPHA_LRELU * v;
                sw[tid][t] = v; mx = fmaxf(mx, v);
            }
            float ssum = 0.f;
            for (int t = 0; t < L; t++) { float ex = expf(sw[tid][t] - mx); sw[tid][t] = ex; ssum += ex; }
            float inv = 1.0f / ssum;
            for (int t = 0; t < L; t++) sw[tid][t] *= inv;
        }
    }
    __syncthreads();
    for (int il = 0; il < 32; il++) {
        int i = i0 + il;
        if (i == 0) continue;
        int jl = i - 23; if (jl < 0) jl = 0;
        int L = i - jl, roff = jl - jlo0;
        float acc = 0.f;
        for (int t = 0; t < L; t++) acc += sw[il][t] * sW[roff + t][tid];
        out[((size_t)b * Nn + i) * Hh + c0 + tid] = eluf(acc);
    }
}

__global__ void gat_logits_kernel(const float* __restrict__ fea_cls,
                                  const float* __restrict__ h2,
                                  const float* __restrict__ U0t,
                                  const float* __restrict__ U2t,
                                  const float* __restrict__ cvec,
                                  float* __restrict__ out)
{
    int n = blockIdx.x;
    int i = n & (Nn - 1);
    int c = threadIdx.x >> 5, l = threadIdx.x & 31;
    const float* frow = fea_cls + (size_t)n * Hh;
    const float* hrow = (i == 0) ? frow : h2 + (size_t)n * Hh;
    const float* u0 = U0t + c * Hh;
    const float* u2 = U2t + c * Hh;
    float acc = 0.f;
    for (int k = l; k < Hh; k += 32)
        acc += frow[k] * u0[k] + hrow[k] * u2[k];
    for (int o = 16; o > 0; o >>= 1) acc += __shfl_down_sync(0xffffffffu, acc, o);
    __shared__ float sh[NCLS];
    if (l == 0) sh[c] = acc + cvec[c];
    __syncthreads();
    if (threadIdx.x == 0) {
        float mx = sh[0];
        for (int k = 1; k < NCLS; k++) mx = fmaxf(mx, sh[k]);
        float e[NCLS], s = 0.f;
        for (int k = 0; k < NCLS; k++) { e[k] = expf(sh[k] - mx); s += e[k]; }
        float inv = 1.0f / s;
        for (int k = 0; k < NCLS; k++) out[n * NCLS + k] = e[k] * inv;
    }
}

__global__ void cls_softmax_kernel(const float* __restrict__ X,
                                   const float* __restrict__ W,
                                   const float* __restrict__ bcls,
                                   float* __restrict__ out)
{
    int n = blockIdx.x;
    int wid = threadIdx.x >> 5, l = threadIdx.x & 31;
    __shared__ float sh[NCLS];
    const float* x = X + (size_t)n * Hh;
    float acc = 0.f;
    for (int t = l; t < Hh; t += 32) acc += x[t] * W[t * NCLS + wid];
    for (int o = 16; o > 0; o >>= 1) acc += __shfl_down_sync(0xffffffffu, acc, o);
    if (l == 0) sh[wid] = acc + bcls[wid];
    __syncthreads();
    if (threadIdx.x == 0) {
        float mx = sh[0];
        for (int k = 1; k < NCLS; k++) mx = fmaxf(mx, sh[k]);
        float e[NCLS], s = 0.f;
        for (int k = 0; k < NCLS; k++) { e[k] = expf(sh[k] - mx); s += e[k]; }
        float inv = 1.0f / s;
        for (int k = 0; k < NCLS; k++) out[n * NCLS + k] = e[k] * inv;
    }
}

__global__ void hmm_kernel(const float* __restrict__ Bprob,
                           const float* __restrict__ hmmA,
                           float* __restrict__ out)
{
    __shared__ float sAT[NCLS * NCLS];
    int tid = threadIdx.x;
    if (tid < NCLS * NCLS) sAT[tid] = hmmA[(tid % NCLS) * NCLS + (tid / NCLS)];
    __syncthreads();
    int gidx = blockIdx.x * 128 + tid;
    int b = gidx >> 8, i = gidx & 255;
    const float* Bp = Bprob + (size_t)b * Nn * NCLS;
    int t0 = i - (BAND - 1); if (t0 < 0) t0 = 0;
    float p[NCLS]; float s = 0.f;
#pragma unroll
    for (int r = 0; r < NCLS; r++) { p[r] = Bp[t0 * NCLS + r]; s += p[r]; }
    float inv = 1.0f / s;
#pragma unroll
    for (int r = 0; r < NCLS; r++) p[r] *= inv;
    for (int t = t0 + 1; t <= i; t++) {
        float q[NCLS]; s = 0.f;
#pragma unroll
        for (int r = 0; r < NCLS; r++) {
            float a = 0.f;
#pragma unroll
            for (int c = 0; c < NCLS; c++) a += sAT[r * NCLS + c] * p[c];
            a *= Bp[t * NCLS + r];
            q[r] = a; s += a;
        }
        inv = 1.0f / s;
#pragma unroll
        for (int r = 0; r < NCLS; r++) p[r] = q[r] * inv;
    }
#pragma unroll
    for (int r = 0; r < NCLS; r++) out[gidx * NCLS + r] = p[r];
}

__global__ void final_kernel(const float* __restrict__ log_gat,
                             const float* __restrict__ log_hmm,
                             const int* __restrict__ labels,
                             float* __restrict__ outLogits)
{
    int r = blockIdx.x * 256 + threadIdx.x;
    float lg[NCLS];
#pragma unroll
    for (int k = 0; k < NCLS; k++) {
        lg[k] = logf(0.5f * (log_gat[r * NCLS + k] + log_hmm[r * NCLS + k]));
        outLogits[r * NCLS + k] = lg[k];
    }
    int lab = labels[r];
    float picked = (lab >= 0) ? lg[lab] : 0.f;
    for (int o = 16; o > 0; o >>= 1) picked += __shfl_down_sync(0xffffffffu, picked, o);
    __shared__ float sh[8];
    if ((threadIdx.x & 31) == 0) sh[threadIdx.x >> 5] = picked;
    __syncthreads();
    if (threadIdx.x == 0) {
        float s = 0.f;
        for (int k = 0; k < 8; k++) s += sh[k];
        g_blocksums[blockIdx.x] = s;
    }
}

__global__ void finalize_kernel(float* d_out, int has_loss)
{
    if (has_loss) {
        float s = 0.f;
        for (int k = 0; k < 32; k++) s += g_blocksums[k];
        d_out[0] = -s / (float)ROWS;
    }
}

// ---------------- host launch ----------------
template <typename T>
static T* sym(const void* symbol)
{
    void* p = nullptr;
    cudaGetSymbolAddress(&p, symbol);
    return (T*)p;
}

static void gemm_tc(const float* A, float* C, const float* Bt, const float* bias,
                    int dotanh, const float* A2 = nullptr, float* C2 = nullptr)
{
    dim3 grid(Hh / BN, ROWS / BM, A2 ? 2 : 1);
    mma_gemm<<<grid, 256, GEMM_SMEM>>>(A, A2 ? A2 : A, C, C2 ? C2 : C,
                                       Bt, bias, dotanh, Hh / BKg);
}

extern "C" void kernel_launch(void* const* d_in, const int* in_sizes, int n_in,
                              void* d_out, int out_size)
{
    (void)in_sizes; (void)n_in;
    const float* hidden_cls = (const float*)d_in[0];
    const float* hidden_emo = (const float*)d_in[1];
    const int*   labels     = (const int*)d_in[3];
    const float* pooler_W   = (const float*)d_in[4];
    const float* pooler_b   = (const float*)d_in[5];
    const float* gat_W      = (const float*)d_in[6];
    const float* gat_a1     = (const float*)d_in[7];
    const float* gat_a2     = (const float*)d_in[8];
    const float* out_W      = (const float*)d_in[9];
    const float* out_a1     = (const float*)d_in[10];
    const float* out_a2     = (const float*)d_in[11];
    const float* lin1_W     = (const float*)d_in[12];
    const float* lin1_b     = (const float*)d_in[13];
    const float* lin0_W     = (const float*)d_in[14];
    const float* lin0_b     = (const float*)d_in[15];
    const float* cls_W      = (const float*)d_in[16];
    const float* cls_b      = (const float*)d_in[17];
    const float* hmm_A      = (const float*)d_in[18];

    float* fea_cls = sym<float>(g_fea_cls);
    float* fea_emo = sym<float>(g_fea_emo);
    float* Wh      = sym<float>(g_Wh);
    float* h1      = sym<float>(g_h1);
    float* Wh2     = sym<float>(g_Wh2);
    float* h2      = sym<float>(g_h2);
    float* s1      = sym<float>(g_s1);
    float* s2      = sym<float>(g_s2);
    float* s1b     = sym<float>(g_s1b);
    float* s2b     = sym<float>(g_s2b);
    float* mean1   = sym<float>(g_mean1);
    float* loggat  = sym<float>(g_loggat);
    float* Bprob   = sym<float>(g_Bprob);
    float* loghmm  = sym<float>(g_loghmm);
    float* poolWt  = sym<float>(g_poolWt);
    float* Wgt     = sym<float>(g_Wgt);
    float* outWt   = sym<float>(g_outWt);
    float* U0t     = sym<float>(g_U0t);
    float* U1t     = sym<float>(g_U1t);
    float* U2t     = sym<float>(g_U2t);
    float* cvec    = sym<float>(g_cvec);

    cudaFuncSetAttribute(mma_gemm, cudaFuncAttributeMaxDynamicSharedMemorySize, GEMM_SMEM);

    int has_loss = (out_size == ROWS * NCLS + 1) ? 1 : 0;
    float* outLogits = has_loss ? ((float*)d_out + 1) : (float*)d_out;

    // 0) weight prep + classifier folding
    {
        dim3 blk(32, 8);
        transpose_kernel<<<dim3(Hh / 32, Hh / 32), blk>>>(pooler_W, poolWt, Hh, Hh);
        transpose_kernel<<<dim3(Hh / 32, Hh / 32), blk>>>(out_W, outWt, Hh, Hh);
        repack_gatWt_kernel<<<(Hh * Hh) / 256, 256>>>(gat_W, Wgt);
        fold_u_kernel<<<2 * Hh, 224>>>(lin0_W, cls_W, U0t, U1t);
        fold_u2_kernel<<<Hh, 224>>>(lin1_W, U1t, U2t);
        fold_cvec_kernel<<<1, 224>>>(lin0_b, lin1_b, cls_W, cls_b, U1t, cvec);
    }

    // 1) poolers (tanh + bias), z-batched into one launch
    gemm_tc(hidden_cls, fea_cls, poolWt, pooler_b, 1, hidden_emo, fea_emo);

    // 2) GAT layer 1
    gemm_tc(fea_cls, Wh, Wgt, nullptr, 0);
    gat_scores_kernel<<<ROWS, 256>>>(Wh, gat_a1, gat_a2, s1, s2);
    mean_rows_kernel<<<dim3(Hh / 256, Bc), 256>>>(Wh, mean1);
    att1_tile_kernel<<<dim3(8, 8, Bc), 128>>>(Wh, s1, s2, h1);
    att1_row0_kernel<<<Bc, 256>>>(mean1, h1);

    // 3) GAT out layer
    gemm_tc(h1, Wh2, outWt, nullptr, 0);
    out_scores_kernel<<<ROWS, 256>>>(Wh2, out_a1, out_a2, s1b, s2b);
    att2_tile_kernel<<<dim3(8, 8, Bc), 128>>>(Wh2, s1b, s2b, h2);

    // 4) folded classifier head
    gat_logits_kernel<<<ROWS, 224>>>(fea_cls, h2, U0t, U2t, cvec, loggat);

    // 5) HMM emission probs
    cls_softmax_kernel<<<ROWS, 224>>>(fea_emo, cls_W, cls_b, Bprob);

    // 6) HMM band filter
    hmm_kernel<<<ROWS / 128, 128>>>(Bprob, hmm_A, loghmm);

    // 7) final logits + loss
    final_kernel<<<ROWS / 256, 256>>>(loggat, loghmm, labels, outLogits);
    finalize_kernel<<<1, 1>>>((float*)d_out, has_loss);
}

// round 7
// speedup vs baseline: 7.6858x; 1.3647x over previous
#include <cuda_runtime.h>
#include <cuda_bf16.h>
#include <math.h>
#include <stdint.h>

// Problem constants
#define Bc   32
#define Nn   256
#define Hh   1024
#define HEADS 8
#define NHID 128
#define NCLS 7
#define BAND 24
#define ROWS (Bc*Nn)          // 8192
#define ALPHA_LRELU 0.2f

typedef __nv_bfloat16 bf16;

// ---------------- device scratch (no allocs allowed) ----------------
__device__ float g_fea_cls[ROWS*Hh];
__device__ float g_fea_emo[ROWS*Hh];
__device__ float g_Wh[ROWS*Hh];
__device__ float g_Wh2[ROWS*Hh];
__device__ float g_h2[ROWS*Hh];
__device__ float g_s1[ROWS*HEADS];
__device__ float g_s2[ROWS*HEADS];
__device__ float g_s1b[ROWS];
__device__ float g_s2b[ROWS];
__device__ float g_mean1[Bc*Hh];
__device__ float g_loggat[ROWS*NCLS];
__device__ float g_Bprob[ROWS*NCLS];
__device__ float g_loghmm[ROWS*NCLS];
__device__ float g_blocksums[32];
// bf16 operands
__device__ bf16 g_hid_cls_bf[ROWS*Hh];
__device__ bf16 g_hid_emo_bf[ROWS*Hh];
__device__ bf16 g_fea_cls_bf[ROWS*Hh];
__device__ bf16 g_h1_bf[ROWS*Hh];
__device__ bf16 g_poolWt[Hh*Hh];   // [N][K] k-major
__device__ bf16 g_Wgt[Hh*Hh];
__device__ bf16 g_outWt[Hh*Hh];
// folded classifier tables
__device__ float g_U0t[NCLS*Hh];
__device__ float g_U1t[NCLS*Hh];
__device__ float g_U2t[NCLS*Hh];
__device__ float g_cvec[NCLS];

// =================== bf16 mma.sync GEMM (3-stage cp.async pipeline) ==========
#define BM 128
#define BN 128
#define BKg 32                                // k elements per stage
#define GSTG 3
#define APITCH 40                             // halves per smem row (80 B)
#define STAGE_BYTES (2 * BM * APITCH * 2)     // A + B = 20480 B
#define GEMM_SMEM (GSTG * STAGE_BYTES)        // 61440 B

__device__ __forceinline__ uint32_t smem_u32(const void* p) {
    uint32_t a;
    asm("{ .reg .u64 t; cvta.to.shared.u64 t, %1; cvt.u32.u64 %0, t; }" : "=r"(a) : "l"(p));
    return a;
}
__device__ __forceinline__ void cp16(uint32_t s, const void* g) {
    asm volatile("cp.async.cg.shared.global [%0], [%1], 16;" :: "r"(s), "l"(g));
}
#define CP_COMMIT() asm volatile("cp.async.commit_group;" ::: "memory")
#define CP_WAIT1()  asm volatile("cp.async.wait_group 1;" ::: "memory")

__device__ __forceinline__ void ldsm4(uint32_t& r0, uint32_t& r1, uint32_t& r2, uint32_t& r3,
                                      uint32_t addr) {
    asm volatile("ldmatrix.sync.aligned.m8n8.x4.shared.b16 {%0,%1,%2,%3}, [%4];"
                 : "=r"(r0), "=r"(r1), "=r"(r2), "=r"(r3) : "r"(addr));
}
__device__ __forceinline__ void mma_bf16(float& d0, float& d1, float& d2, float& d3,
                                         uint32_t a0, uint32_t a1, uint32_t a2, uint32_t a3,
                                         uint32_t b0, uint32_t b1) {
    asm volatile("mma.sync.aligned.m16n8k16.row.col.f32.bf16.bf16.f32 "
                 "{%0,%1,%2,%3}, {%4,%5,%6,%7}, {%8,%9}, {%0,%1,%2,%3};"
                 : "+f"(d0), "+f"(d1), "+f"(d2), "+f"(d3)
                 : "r"(a0), "r"(a1), "r"(a2), "r"(a3), "r"(b0), "r"(b1));
}

// stage layout: [stage][ A: 128 x APITCH | B: 128 x APITCH ] halves
__device__ __forceinline__ void gemm_load_stage(uint32_t sb, int stage, int tid,
                                                const bf16* Ag, const bf16* Bg) {
    uint32_t abase = sb + stage * STAGE_BYTES;
    uint32_t bbase = abase + BM * APITCH * 2;
#pragma unroll
    for (int i = 0; i < 2; i++) {
        int idx = tid + 256 * i;        // 0..511
        int r = idx >> 2;               // 0..127
        int q = idx & 3;                // 16B chunk (8 halves)
        cp16(abase + r * (APITCH * 2) + q * 16, Ag + (size_t)r * Hh + q * 8);
        cp16(bbase + r * (APITCH * 2) + q * 16, Bg + (size_t)r * Hh + q * 8);
    }
}

// z-batched: blockIdx.z selects (Aa,Ca,Cbfa) or (Ab,Cb,Cbfb). B shared.
__global__ void __launch_bounds__(256, 2)
mma_gemm(const bf16* __restrict__ Aa, const bf16* __restrict__ Ab,
         float* __restrict__ Ca, float* __restrict__ Cb,
         bf16* __restrict__ Cbfa, bf16* __restrict__ Cbfb,
         const bf16* __restrict__ Bt,
         const float* __restrict__ bias, int dotanh, int T)
{
    extern __shared__ char smem[];
    uint32_t sb = smem_u32(smem);
    const int tid = threadIdx.x;
    const int wid = tid >> 5, lane = tid & 31;
    const int wm = wid >> 2, wn = wid & 3;   // 2x4 warp grid, warp tile 64x32
    const int n0 = blockIdx.x * BN;
    const size_t m0 = (size_t)blockIdx.y * BM;
    const bf16* A = (blockIdx.z == 0) ? Aa : Ab;
    float* C = (blockIdx.z == 0) ? Ca : Cb;
    bf16* Cbf = (blockIdx.z == 0) ? Cbfa : Cbfb;

    float acc[4][4][4];
#pragma unroll
    for (int mi = 0; mi < 4; mi++)
#pragma unroll
        for (int ni = 0; ni < 4; ni++)
#pragma unroll
            for (int k = 0; k < 4; k++) acc[mi][ni][k] = 0.f;

    const bf16* Arow = A + m0 * Hh;
    const bf16* Brow = Bt + (size_t)n0 * Hh;

    gemm_load_stage(sb, 0, tid, Arow, Brow);
    CP_COMMIT();
    gemm_load_stage(sb, 1, tid, Arow + BKg, Brow + BKg);
    CP_COMMIT();

    const int tl = lane >> 3;          // ldmatrix tile selector
    const int l7 = lane & 7;

    for (int t = 0; t < T; t++) {
        CP_WAIT1();
        __syncthreads();
        int nc = t + 2;
        if (nc < T)
            gemm_load_stage(sb, nc % GSTG, tid, Arow + nc * BKg, Brow + nc * BKg);
        CP_COMMIT();   // always commit to keep group counting sound

        uint32_t sA = sb + (t % GSTG) * STAGE_BYTES;
        uint32_t sB = sA + BM * APITCH * 2;
#pragma unroll
        for (int ks = 0; ks < 2; ks++) {
            uint32_t a[4][4];
#pragma unroll
            for (int mi = 0; mi < 4; mi++) {
                int row = wm * 64 + mi * 16 + (tl & 1) * 8 + l7;
                int col = ks * 16 + (tl >> 1) * 8;
                ldsm4(a[mi][0], a[mi][1], a[mi][2], a[mi][3],
                      sA + row * (APITCH * 2) + col * 2);
            }
            uint32_t bq[2][4];
#pragma unroll
            for (int nn = 0; nn < 2; nn++) {
                int row = wn * 32 + nn * 16 + (tl >> 1) * 8 + l7;
                int col = ks * 16 + (tl & 1) * 8;
                ldsm4(bq[nn][0], bq[nn][1], bq[nn][2], bq[nn][3],
                      sB + row * (APITCH * 2) + col * 2);
            }
#pragma unroll
            for (int mi = 0; mi < 4; mi++)
#pragma unroll
                for (int ni = 0; ni < 4; ni++)
                    mma_bf16(acc[mi][ni][0], acc[mi][ni][1], acc[mi][ni][2], acc[mi][ni][3],
                             a[mi][0], a[mi][1], a[mi][2], a[mi][3],
                             bq[ni >> 1][(ni & 1) * 2], bq[ni >> 1][(ni & 1) * 2 + 1]);
        }
    }

    const int lq = lane >> 2;
    const int lr = lane & 3;
#pragma unroll
    for (int mi = 0; mi < 4; mi++) {
        int row = (int)m0 + wm * 64 + mi * 16 + lq;
#pragma unroll
        for (int ni = 0; ni < 4; ni++) {
            int col = n0 + wn * 32 + ni * 8 + lr * 2;
            float b0 = 0.f, b1 = 0.f;
            if (bias) { b0 = bias[col]; b1 = bias[col + 1]; }
            float2 v0, v1;
            v0.x = acc[mi][ni][0] + b0; v0.y = acc[mi][ni][1] + b1;
            v1.x = acc[mi][ni][2] + b0; v1.y = acc[mi][ni][3] + b1;
            if (dotanh) {
                v0.x = tanhf(v0.x); v0.y = tanhf(v0.y);
                v1.x = tanhf(v1.x); v1.y = tanhf(v1.y);
            }
            *(float2*)(C + (size_t)row * Hh + col) = v0;
            *(float2*)(C + (size_t)(row + 8) * Hh + col) = v1;
            if (Cbf) {
                __nv_bfloat162 w0, w1;
                w0.x = __float2bfloat16_rn(v0.x); w0.y = __float2bfloat16_rn(v0.y);
                w1.x = __float2bfloat16_rn(v1.x); w1.y = __float2bfloat16_rn(v1.y);
                *(__nv_bfloat162*)(Cbf + (size_t)row * Hh + col) = w0;
                *(__nv_bfloat162*)(Cbf + (size_t)(row + 8) * Hh + col) = w1;
            }
        }
    }
}

// =================== weight prep / converts ===================
// out[N][K] (bf16) = in[K][N] (fp32)
__global__ void transpose_bf_kernel(const float* __restrict__ in, bf16* __restrict__ out,
                                    int K, int N)
{
    __shared__ float tile[32][33];
    int k0 = blockIdx.y * 32, n0 = blockIdx.x * 32;
    int tx = threadIdx.x, ty = threadIdx.y;
    for (int r = ty; r < 32; r += 8) tile[r][tx] = in[(size_t)(k0 + r) * N + n0 + tx];
    __syncthreads();
    for (int r = ty; r < 32; r += 8)
        out[(size_t)(n0 + r) * K + k0 + tx] = __float2bfloat16_rn(tile[tx][r]);
}
__global__ void repack_gatWt_kernel(const float* __restrict__ gw, bf16* __restrict__ Wgt)
{
    int idx = blockIdx.x * 256 + threadIdx.x;   // n*1024 + f
    int n = idx >> 10, f = idx & 1023;
    int h = n >> 7, d = n & 127;
    Wgt[idx] = __float2bfloat16_rn(gw[((size_t)(h << 10 | f)) * NHID + d]);
}
// fp32 -> bf16 bulk convert, two tensors via blockIdx.y
__global__ void cvt_bf_kernel(const float* __restrict__ a, const float* __restrict__ b,
                              bf16* __restrict__ oa, bf16* __restrict__ ob)
{
    const float* src = blockIdx.y ? b : a;
    bf16* dst = blockIdx.y ? ob : oa;
    int idx = (blockIdx.x * 256 + threadIdx.x) * 4;
    float4 v = *(const float4*)(src + idx);
    __nv_bfloat162 w0, w1;
    w0.x = __float2bfloat16_rn(v.x); w0.y = __float2bfloat16_rn(v.y);
    w1.x = __float2bfloat16_rn(v.z); w1.y = __float2bfloat16_rn(v.w);
    *(__nv_bfloat162*)(dst + idx) = w0;
    *(__nv_bfloat162*)(dst + idx + 2) = w1;
}

__global__ void fold_u_kernel(const float* __restrict__ lin0W,
                              const float* __restrict__ clsW,
                              float* __restrict__ U0t, float* __restrict__ U1t)
{
    int r = blockIdx.x;
    int c = threadIdx.x >> 5, l = threadIdx.x & 31;
    const float* row = lin0W + (size_t)r * Hh;
    float acc = 0.f;
    for (int k = l; k < Hh; k += 32) acc += row[k] * clsW[k * NCLS + c];
    for (int o = 16; o > 0; o >>= 1) acc += __shfl_down_sync(0xffffffffu, acc, o);
    if (l == 0) {
        if (r < Hh) U0t[c * Hh + r] = acc;
        else        U1t[c * Hh + (r - Hh)] = acc;
    }
}
__global__ void fold_u2_kernel(const float* __restrict__ lin1W,
                               const float* __restrict__ U1t,
                               float* __restrict__ U2t)
{
    int r = blockIdx.x;
    int c = threadIdx.x >> 5, l = threadIdx.x & 31;
    const float* row = lin1W + (size_t)r * Hh;
    const float* u1 = U1t + c * Hh;
    float acc = 0.f;
    for (int k = l; k < Hh; k += 32) acc += row[k] * u1[k];
    for (int o = 16; o > 0; o >>= 1) acc += __shfl_down_sync(0xffffffffu, acc, o);
    if (l == 0) U2t[c * Hh + r] = acc;
}
__global__ void fold_cvec_kernel(const float* __restrict__ lin0b,
                                 const float* __restrict__ lin1b,
                                 const float* __restrict__ clsW,
                                 const float* __restrict__ clsb,
                                 const float* __restrict__ U1t,
                                 float* __restrict__ cvec)
{
    int c = threadIdx.x >> 5, l = threadIdx.x & 31;
    float acc = 0.f;
    for (int k = l; k < Hh; k += 32)
        acc += lin0b[k] * clsW[k * NCLS + c] + lin1b[k] * U1t[c * Hh + k];
    for (int o = 16; o > 0; o >>= 1) acc += __shfl_down_sync(0xffffffffu, acc, o);
    if (l == 0) cvec[c] = acc + clsb[c];
}

// =================== small kernels ===================
__global__ void gat_scores_kernel(const float* __restrict__ Wh,
                                  const float* __restrict__ a1,
                                  const float* __restrict__ a2,
                                  float* __restrict__ s1, float* __restrict__ s2)
{
    int n = blockIdx.x;
    int w = threadIdx.x >> 5, l = threadIdx.x & 31;
    const float* row = Wh + (size_t)n * Hh + w * NHID;
    float x1 = 0.f, x2 = 0.f;
#pragma unroll
    for (int t = 0; t < 4; t++) {
        float v = row[l + 32 * t];
        x1 += v * a1[w * NHID + l + 32 * t];
        x2 += v * a2[w * NHID + l + 32 * t];
    }
    for (int o = 16; o > 0; o >>= 1) {
        x1 += __shfl_down_sync(0xffffffffu, x1, o);
        x2 += __shfl_down_sync(0xffffffffu, x2, o);
    }
    if (l == 0) { s1[n * HEADS + w] = x1; s2[n * HEADS + w] = x2; }
}

__global__ void mean_rows_kernel(const float* __restrict__ X, float* __restrict__ out)
{
    int b = blockIdx.y;
    int c = blockIdx.x * 256 + threadIdx.x;
    const float* p = X + (size_t)b * Nn * Hh + c;
    float s = 0.f;
    for (int n = 0; n < Nn; n++) s += p[(size_t)n * Hh];
    out[b * Hh + c] = s * (1.0f / Nn);
}

__device__ __forceinline__ float eluf(float x) { return x > 0.f ? x : expf(x) - 1.0f; }

// band attention layer 1 (per-head), writes bf16 h1
__global__ void att1_tile_kernel(const float* __restrict__ Wh,
                                 const float* __restrict__ s1,
                                 const float* __restrict__ s2,
                                 bf16* __restrict__ h1)
{
    __shared__ float sW[54][128];
    __shared__ float sw[32][24];
    int b = blockIdx.z, h = blockIdx.y, it = blockIdx.x;
    int i0 = it * 32;
    int jlo0 = i0 - 23; if (jlo0 < 0) jlo0 = 0;
    int nrows = (i0 + 30) - jlo0 + 1;
    int tid = threadIdx.x;
    const float* base = Wh + (size_t)b * Nn * Hh + h * NHID;
    for (int rr = 0; rr < nrows; rr++)
        sW[rr][tid] = base[(size_t)(jlo0 + rr) * Hh + tid];
    if (tid < 32) {
        int i = i0 + tid;
        if (i > 0) {
            int jl = i - 23; if (jl < 0) jl = 0;
            int L = i - jl;
            float si = s1[((size_t)b * Nn + i) * HEADS + h];
            float mx = -1e30f;
            for (int t = 0; t < L; t++) {
                float v = si + s2[((size_t)b * Nn + jl + t) * HEADS + h];
                v = v > 0.f ? v : ALPHA_LRELU * v;
                sw[tid][t] = v; mx = fmaxf(mx, v);
            }
            float ssum = 0.f;
            for (int t = 0; t < L; t++) { float ex = expf(sw[tid][t] - mx); sw[tid][t] = ex; ssum += ex; }
            float inv = 1.0f / ssum;
            for (int t = 0; t < L; t++) sw[tid][t] *= inv;
        }
    }
    __syncthreads();
    for (int il = 0; il < 32; il++) {
        int i = i0 + il;
        if (i == 0) continue;
        int jl = i - 23; if (jl < 0) jl = 0;
        int L = i - jl, roff = jl - jlo0;
        float acc = 0.f;
        for (int t = 0; t < L; t++) acc += sw[il][t] * sW[roff + t][tid];
        h1[((size_t)b * Nn + i) * Hh + h * NHID + tid] = __float2bfloat16_rn(eluf(acc));
    }
}

__global__ void att1_row0_kernel(const float* __restrict__ mean1, bf16* __restrict__ h1)
{
    int b = blockIdx.x;
    for (int c = threadIdx.x; c < Hh; c += 256)
        h1[(size_t)b * Nn * Hh + c] = __float2bfloat16_rn(eluf(mean1[b * Hh + c]));
}

__global__ void out_scores_kernel(const float* __restrict__ Wh2,
                                  const float* __restrict__ a1,
                                  const float* __restrict__ a2,
                                  float* __restrict__ s1, float* __restrict__ s2)
{
    int n = blockIdx.x;
    int tid = threadIdx.x;
    float x1 = 0.f, x2 = 0.f;
    const float* x = Wh2 + (size_t)n * Hh;
    for (int c = tid; c < Hh; c += 256) { float v = x[c]; x1 += v * a1[c]; x2 += v * a2[c]; }
    __shared__ float sh1[8], sh2[8];
    for (int o = 16; o > 0; o >>= 1) {
        x1 += __shfl_down_sync(0xffffffffu, x1, o);
        x2 += __shfl_down_sync(0xffffffffu, x2, o);
    }
    if ((tid & 31) == 0) { sh1[tid >> 5] = x1; sh2[tid >> 5] = x2; }
    __syncthreads();
    if (tid == 0) {
        float t1 = 0.f, t2 = 0.f;
        for (int k = 0; k < 8; k++) { t1 += sh1[k]; t2 += sh2[k]; }
        s1[n] = t1; s2[n] = t2;
    }
}

__global__ void att2_tile_kernel(const float* __restrict__ Wh2,
                                 const float* __restrict__ s1,
                                 const float* __restrict__ s2,
                                 float* __restrict__ out)
{
    __shared__ float sW[54][128];
    __shared__ float sw[32][24];
    int b = blockIdx.z, ct = blockIdx.y, it = blockIdx.x;
    int i0 = it * 32, c0 = ct * 128;
    int jlo0 = i0 - 23; if (jlo0 < 0) jlo0 = 0;
    int nrows = (i0 + 30) - jlo0 + 1;
    int tid = threadIdx.x;
    const float* base = Wh2 + (size_t)b * Nn * Hh + c0;
    for (int rr = 0; rr < nrows; rr++)
        sW[rr][tid] = base[(size_t)(jlo0 + rr) * Hh + tid];
    if (tid < 32) {
        int i = i0 + tid;
        if (i > 0) {
            int jl = i - 23; if (jl < 0) jl = 0;
            int L = i - jl;
            float si = s1[(size_t)b * Nn + i];
            float mx = -1e30f;
            for (int t = 0; t < L; t++) {
                float v = si + s2[(size_t)b * Nn + jl + t];
                v = v > 0.f ? v : ALPHA_LRELU * v;
                sw[tid][t] = v; mx = fmaxf(mx, v);
            }
            float ssum = 0.f;
            for (int t = 0; t < L; t++) { float ex = expf(sw[tid][t] - mx); sw[tid][t] = ex; ssum += ex; }
            float inv = 1.0f / ssum;
            for (int t = 0; t < L; t++) sw[tid][t] *= inv;
        }
    }
    __syncthreads();
    for (int il = 0; il < 32; il++) {
        int i = i0 + il;
        if (i == 0) continue;
        int jl = i - 23; if (jl < 0) jl = 0;
        int L = i - jl, roff = jl - jlo0;
        float acc = 0.f;
        for (int t = 0; t < L; t++) acc += sw[il][t] * sW[roff + t][tid];
        out[((size_t)b * Nn + i) * Hh + c0 + tid] = eluf(acc);
    }
}

__global__ void gat_logits_kernel(const float* __restrict__ fea_cls,
                                  const float* __restrict__ h2,
                                  const float* __restrict__ U0t,
                                  const float* __restrict__ U2t,
                                  const float* __restrict__ cvec,
                                  float* __restrict__ out)
{
    int n = blockIdx.x;
    int i = n & (Nn - 1);
    int c = threadIdx.x >> 5, l = threadIdx.x & 31;
    const float* frow = fea_cls + (size_t)n * Hh;
    const float* hrow = (i == 0) ? frow : h2 + (size_t)n * Hh;
    const float* u0 = U0t + c * Hh;
    const float* u2 = U2t + c * Hh;
    float acc = 0.f;
    for (int k = l; k < Hh; k += 32)
        acc += frow[k] * u0[k] + hrow[k] * u2[k];
    for (int o = 16; o > 0; o >>= 1) acc += __shfl_down_sync(0xffffffffu, acc, o);
    __shared__ float sh[NCLS];
    if (l == 0) sh[c] = acc + cvec[c];
    __syncthreads();
    if (threadIdx.x == 0) {
        float mx = sh[0];
        for (int k = 1; k < NCLS; k++) mx = fmaxf(mx, sh[k]);
        float e[NCLS], s = 0.f;
        for (int k = 0; k < NCLS; k++) { e[k] = expf(sh[k] - mx); s += e[k]; }
        float inv = 1.0f / s;
        for (int k = 0; k < NCLS; k++) out[n * NCLS + k] = e[k] * inv;
    }
}

__global__ void cls_softmax_kernel(const float* __restrict__ X,
                                   const float* __restrict__ W,
                                   const float* __restrict__ bcls,
                                   float* __restrict__ out)
{
    int n = blockIdx.x;
    int wid = threadIdx.x >> 5, l = threadIdx.x & 31;
    __shared__ float sh[NCLS];
    const float* x = X + (size_t)n * Hh;
    float acc = 0.f;
    for (int t = l; t < Hh; t += 32) acc += x[t] * W[t * NCLS + wid];
    for (int o = 16; o > 0; o >>= 1) acc += __shfl_down_sync(0xffffffffu, acc, o);
    if (l == 0) sh[wid] = acc + bcls[wid];
    __syncthreads();
    if (threadIdx.x == 0) {
        float mx = sh[0];
        for (int k = 1; k < NCLS; k++) mx = fmaxf(mx, sh[k]);
        float e[NCLS], s = 0.f;
        for (int k = 0; k < NCLS; k++) { e[k] = expf(sh[k] - mx); s += e[k]; }
        float inv = 1.0f / s;
        for (int k = 0; k < NCLS; k++) out[n * NCLS + k] = e[k] * inv;
    }
}

__global__ void hmm_kernel(const float* __restrict__ Bprob,
                           const float* __restrict__ hmmA,
                           float* __restrict__ out)
{
    __shared__ float sAT[NCLS * NCLS];
    int tid = threadIdx.x;
    if (tid < NCLS * NCLS) sAT[tid] = hmmA[(tid % NCLS) * NCLS + (tid / NCLS)];
    __syncthreads();
    int gidx = blockIdx.x * 128 + tid;
    int b = gidx >> 8, i = gidx & 255;
    const float* Bp = Bprob + (size_t)b * Nn * NCLS;
    int t0 = i - (BAND - 1); if (t0 < 0) t0 = 0;
    float p[NCLS]; float s = 0.f;
#pragma unroll
    for (int r = 0; r < NCLS; r++) { p[r] = Bp[t0 * NCLS + r]; s += p[r]; }
    float inv = 1.0f / s;
#pragma unroll
    for (int r = 0; r < NCLS; r++) p[r] *= inv;
    for (int t = t0 + 1; t <= i; t++) {
        float q[NCLS]; s = 0.f;
#pragma unroll
        for (int r = 0; r < NCLS; r++) {
            float a = 0.f;
#pragma unroll
            for (int c = 0; c < NCLS; c++) a += sAT[r * NCLS + c] * p[c];
            a *= Bp[t * NCLS + r];
            q[r] = a; s += a;
        }
        inv = 1.0f / s;
#pragma unroll
        for (int r = 0; r < NCLS; r++) p[r] = q[r] * inv;
    }
#pragma unroll
    for (int r = 0; r < NCLS; r++) out[gidx * NCLS + r] = p[r];
}

__global__ void final_kernel(const float* __restrict__ log_gat,
                             const float* __restrict__ log_hmm,
                             const int* __restrict__ labels,
                             float* __restrict__ outLogits)
{
    int r = blockIdx.x * 256 + threadIdx.x;
    float lg[NCLS];
#pragma unroll
    for (int k = 0; k < NCLS; k++) {
        lg[k] = logf(0.5f * (log_gat[r * NCLS + k] + log_hmm[r * NCLS + k]));
        outLogits[r * NCLS + k] = lg[k];
    }
    int lab = labels[r];
    float picked = (lab >= 0) ? lg[lab] : 0.f;
    for (int o = 16; o > 0; o >>= 1) picked += __shfl_down_sync(0xffffffffu, picked, o);
    __shared__ float sh[8];
    if ((threadIdx.x & 31) == 0) sh[threadIdx.x >> 5] = picked;
    __syncthreads();
    if (threadIdx.x == 0) {
        float s = 0.f;
        for (int k = 0; k < 8; k++) s += sh[k];
        g_blocksums[blockIdx.x] = s;
    }
}

__global__ void finalize_kernel(float* d_out, int has_loss)
{
    if (has_loss) {
        float s = 0.f;
        for (int k = 0; k < 32; k++) s += g_blocksums[k];
        d_out[0] = -s / (float)ROWS;
    }
}

// ---------------- host launch ----------------
template <typename T>
static T* sym(const void* symbol)
{
    void* p = nullptr;
    cudaGetSymbolAddress(&p, symbol);
    return (T*)p;
}

static void gemm_tc(const bf16* A, float* C, bf16* Cbf, const bf16* Bt,
                    const float* bias, int dotanh,
                    const bf16* A2 = nullptr, float* C2 = nullptr, bf16* Cbf2 = nullptr)
{
    dim3 grid(Hh / BN, ROWS / BM, A2 ? 2 : 1);
    mma_gemm<<<grid, 256, GEMM_SMEM>>>(A, A2 ? A2 : A, C, C2 ? C2 : C,
                                       Cbf, Cbf2, Bt, bias, dotanh, Hh / BKg);
}

extern "C" void kernel_launch(void* const* d_in, const int* in_sizes, int n_in,
                              void* d_out, int out_size)
{
    (void)in_sizes; (void)n_in;
    const float* hidden_cls = (const float*)d_in[0];
    const float* hidden_emo = (const float*)d_in[1];
    const int*   labels     = (const int*)d_in[3];
    const float* pooler_W   = (const float*)d_in[4];
    const float* pooler_b   = (const float*)d_in[5];
    const float* gat_W      = (const float*)d_in[6];
    const float* gat_a1     = (const float*)d_in[7];
    const float* gat_a2     = (const float*)d_in[8];
    const float* out_W      = (const float*)d_in[9];
    const float* out_a1     = (const float*)d_in[10];
    const float* out_a2     = (const float*)d_in[11];
    const float* lin1_W     = (const float*)d_in[12];
    const float* lin1_b     = (const float*)d_in[13];
    const float* lin0_W     = (const float*)d_in[14];
    const float* lin0_b     = (const float*)d_in[15];
    const float* cls_W      = (const float*)d_in[16];
    const float* cls_b      = (const float*)d_in[17];
    const float* hmm_A      = (const float*)d_in[18];

    float* fea_cls = sym<float>(g_fea_cls);
    float* fea_emo = sym<float>(g_fea_emo);
    float* Wh      = sym<float>(g_Wh);
    float* Wh2     = sym<float>(g_Wh2);
    float* h2      = sym<float>(g_h2);
    float* s1      = sym<float>(g_s1);
    float* s2      = sym<float>(g_s2);
    float* s1b     = sym<float>(g_s1b);
    float* s2b     = sym<float>(g_s2b);
    float* mean1   = sym<float>(g_mean1);
    float* loggat  = sym<float>(g_loggat);
    float* Bprob   = sym<float>(g_Bprob);
    float* loghmm  = sym<float>(g_loghmm);
    bf16* hidcbf   = sym<bf16>(g_hid_cls_bf);
    bf16* hidebf   = sym<bf16>(g_hid_emo_bf);
    bf16* feacbf   = sym<bf16>(g_fea_cls_bf);
    bf16* h1bf     = sym<bf16>(g_h1_bf);
    bf16* poolWt   = sym<bf16>(g_poolWt);
    bf16* Wgt      = sym<bf16>(g_Wgt);
    bf16* outWt    = sym<bf16>(g_outWt);
    float* U0t     = sym<float>(g_U0t);
    float* U1t     = sym<float>(g_U1t);
    float* U2t     = sym<float>(g_U2t);
    float* cvec    = sym<float>(g_cvec);

    cudaFuncSetAttribute(mma_gemm, cudaFuncAttributeMaxDynamicSharedMemorySize, GEMM_SMEM);

    int has_loss = (out_size == ROWS * NCLS + 1) ? 1 : 0;
    float* outLogits = has_loss ? ((float*)d_out + 1) : (float*)d_out;

    // 0) weight prep + input converts + classifier folding
    {
        dim3 blk(32, 8);
        transpose_bf_kernel<<<dim3(Hh / 32, Hh / 32), blk>>>(pooler_W, poolWt, Hh, Hh);
        transpose_bf_kernel<<<dim3(Hh / 32, Hh / 32), blk>>>(out_W, outWt, Hh, Hh);
        repack_gatWt_kernel<<<(Hh * Hh) / 256, 256>>>(gat_W, Wgt);
        cvt_bf_kernel<<<dim3(ROWS * Hh / 1024, 2), 256>>>(hidden_cls, hidden_emo, hidcbf, hidebf);
        fold_u_kernel<<<2 * Hh, 224>>>(lin0_W, cls_W, U0t, U1t);
        fold_u2_kernel<<<Hh, 224>>>(lin1_W, U1t, U2t);
        fold_cvec_kernel<<<1, 224>>>(lin0_b, lin1_b, cls_W, cls_b, U1t, cvec);
    }

    // 1) poolers (tanh + bias), z-batched; fea_cls also emitted as bf16
    gemm_tc(hidcbf, fea_cls, feacbf, poolWt, pooler_b, 1, hidebf, fea_emo, nullptr);

    // 2) GAT layer 1
    gemm_tc(feacbf, Wh, nullptr, Wgt, nullptr, 0);
    gat_scores_kernel<<<ROWS, 256>>>(Wh, gat_a1, gat_a2, s1, s2);
    mean_rows_kernel<<<dim3(Hh / 256, Bc), 256>>>(Wh, mean1);
    att1_tile_kernel<<<dim3(8, 8, Bc), 128>>>(Wh, s1, s2, h1bf);
    att1_row0_kernel<<<Bc, 256>>>(mean1, h1bf);

    // 3) GAT out layer
    gemm_tc(h1bf, Wh2, nullptr, outWt, nullptr, 0);
    out_scores_kernel<<<ROWS, 256>>>(Wh2, out_a1, out_a2, s1b, s2b);
    att2_tile_kernel<<<dim3(8, 8, Bc), 128>>>(Wh2, s1b, s2b, h2);

    // 4) folded classifier head
    gat_logits_kernel<<<ROWS, 224>>>(fea_cls, h2, U0t, U2t, cvec, loggat);

    // 5) HMM emission probs
    cls_softmax_kernel<<<ROWS, 224>>>(fea_emo, cls_W, cls_b, Bprob);

    // 6) HMM band filter
    hmm_kernel<<<ROWS / 128, 128>>>(Bprob, hmm_A, loghmm);

    // 7) final logits + loss
    final_kernel<<<ROWS / 256, 256>>>(loggat, loghmm, labels, outLogits);
    finalize_kernel<<<1, 1>>>((float*)d_out, has_loss);
}